// round 6
// baseline (speedup 1.0000x reference)
#include <cuda_runtime.h>
#include <cstdint>

// ---------------------------------------------------------------------------
// TempoJelly R5b: INT8 tensor-core path with exact integer accumulation.
//   s2 = ((x @ W1^T >= 1) @ W2^T >= 1), x binary.
//
//  - activations {0,1} -> int8 (exact)
//  - per output column j: q_k = round(w_k * S_j), |q| <= 2^20,
//    balanced base-128 digits q = a*2^14 + b*2^7 + c, a,b,c in [-64,64] (s8)
//  - GEMM (mma.m16n8k32.s8) computes Sa=sum x*a, Sb=sum x*b EXACTLY (s32)
//  - epilogue: t2 = Sa*2^14 + Sb*2^7; spike = (t2 >= S_j) unless
//    |t2 - S_j| <= eps2_j = sum|c| + sum|w*S - q| + margin  -> candidate
//  - candidate fixup 1: t = t2 + sum x*c (dp4a); remaining bound eps3 tiny
//  - candidate fixup 2 (rare): exact fp32 dot
// ---------------------------------------------------------------------------

#define B_ROWS  4096
#define IN_K    3136
#define IN_KPAD 3200
#define FEAT    6272
#define OUT_N   500
#define OUT_PAD 512
#define MAXC    (1 << 21)

// ---------------- static scratch --------------------------------------------
__device__ __align__(16) int8_t g_xi [(size_t)B_ROWS * IN_KPAD];
__device__ __align__(16) int8_t g_w1a[(size_t)FEAT * IN_KPAD];
__device__ __align__(16) int8_t g_w1b[(size_t)FEAT * IN_KPAD];
__device__ __align__(16) int8_t g_w1c[(size_t)FEAT * IN_KPAD];
__device__ __align__(16) int8_t g_w2a[(size_t)OUT_PAD * FEAT];
__device__ __align__(16) int8_t g_w2b[(size_t)OUT_PAD * FEAT];
__device__ __align__(16) int8_t g_w2c[(size_t)OUT_PAD * FEAT];
__device__ __align__(16) int8_t g_s1i[(size_t)B_ROWS * FEAT];
__device__ float g_S1[FEAT],    g_e21[FEAT],    g_e31[FEAT];
__device__ float g_S2[OUT_PAD], g_e22[OUT_PAD], g_e32[OUT_PAD];
__device__ uint32_t  g_crc1[MAXC];
__device__ long long g_ct1 [MAXC];
__device__ uint32_t  g_crc2[MAXC];
__device__ long long g_ct2 [MAXC];
__device__ uint32_t  g_crc1e[MAXC];
__device__ uint32_t  g_crc2e[MAXC];
__device__ uint32_t  g_cnt[4];   // cand1, cand1e, cand2, cand2e

// ---------------- PTX helpers ------------------------------------------------
__device__ __forceinline__ uint32_t smem_u32(const void* p) {
    return (uint32_t)__cvta_generic_to_shared(p);
}
__device__ __forceinline__ uint32_t sw128(uint32_t off) {
    return off ^ ((off >> 3) & 0x70);
}
__device__ __forceinline__ int dp4a_s(uint32_t a, uint32_t b, int c) {
    return __dp4a((int)a, (int)b, c);
}

#define CP_ASYNC16(smaddr, gptr)                                               \
    asm volatile("cp.async.cg.shared.global [%0], [%1], 16;"                   \
                 :: "r"(smaddr), "l"(gptr))
#define CP_COMMIT() asm volatile("cp.async.commit_group;" ::: "memory")
#define CP_WAIT(n)  asm volatile("cp.async.wait_group %0;" :: "n"(n) : "memory")

#define LDSM_X4(r, addr)                                                       \
    asm volatile("ldmatrix.sync.aligned.m8n8.x4.shared.b16 {%0,%1,%2,%3}, [%4];" \
                 : "=r"((r)[0]), "=r"((r)[1]), "=r"((r)[2]), "=r"((r)[3])      \
                 : "r"(addr))

#define MMAS8(cc, aa, b0, b1)                                                  \
    asm volatile("mma.sync.aligned.m16n8k32.row.col.s32.s8.s8.s32 "            \
                 "{%0,%1,%2,%3},{%4,%5,%6,%7},{%8,%9},{%0,%1,%2,%3};"          \
                 : "+r"((cc)[0]), "+r"((cc)[1]), "+r"((cc)[2]), "+r"((cc)[3])  \
                 : "r"((aa)[0]), "r"((aa)[1]), "r"((aa)[2]), "r"((aa)[3]),     \
                   "r"(b0), "r"(b1))

// ---------------- prep kernels -----------------------------------------------
__global__ void reset_kernel() {
    if (threadIdx.x < 4) g_cnt[threadIdx.x] = 0;
}

// x (fp32 0/1) -> int8 0/1, K padded 3136 -> 3200 with zeros
__global__ void cvt_x_s8(const float* __restrict__ x, int8_t* __restrict__ xi) {
    const size_t n4 = (size_t)B_ROWS * IN_KPAD / 4;
    size_t i = (size_t)blockIdx.x * blockDim.x + threadIdx.x;
    const size_t stride = (size_t)gridDim.x * blockDim.x;
    for (; i < n4; i += stride) {
        const int row = (int)(i / (IN_KPAD / 4));
        const int k4  = (int)(i % (IN_KPAD / 4)) * 4;
        uchar4 o = make_uchar4(0, 0, 0, 0);
        if (k4 < IN_K) {   // IN_K % 4 == 0, so fully in or fully pad
            const float4 v = *reinterpret_cast<const float4*>(
                x + (size_t)row * IN_K + k4);
            o.x = (v.x != 0.0f); o.y = (v.y != 0.0f);
            o.z = (v.z != 0.0f); o.w = (v.w != 0.0f);
        }
        *reinterpret_cast<uchar4*>(xi + i * 4) = o;
    }
}

// One warp per output column: quantize w*S into 3 balanced s8 digits + bounds.
__global__ void quant_w(const float* __restrict__ W, int n_rows, int rows_pad,
                        int K, int Kpad,
                        int8_t* __restrict__ Wa, int8_t* __restrict__ Wb,
                        int8_t* __restrict__ Wc,
                        float* __restrict__ S, float* __restrict__ e2,
                        float* __restrict__ e3) {
    const int wid  = threadIdx.x >> 5;
    const int lane = threadIdx.x & 31;
    const int row  = blockIdx.x * (blockDim.x >> 5) + wid;
    if (row >= rows_pad) return;

    if (row >= n_rows) {   // pad row: zero digits, never-candidate bounds
        for (int i = lane * 4; i < Kpad; i += 128) {
            *reinterpret_cast<char4*>(Wa + (size_t)row * Kpad + i) = make_char4(0,0,0,0);
            *reinterpret_cast<char4*>(Wb + (size_t)row * Kpad + i) = make_char4(0,0,0,0);
            *reinterpret_cast<char4*>(Wc + (size_t)row * Kpad + i) = make_char4(0,0,0,0);
        }
        if (lane == 0) { S[row] = 3.0e9f; e2[row] = 0.0f; e3[row] = 0.0f; }
        return;
    }

    // pass 1: row max-abs
    float mx = 0.0f;
    for (int i = lane * 4; i < K; i += 128) {
        const float4 v = *reinterpret_cast<const float4*>(W + (size_t)row * K + i);
        mx = fmaxf(mx, fmaxf(fmaxf(fabsf(v.x), fabsf(v.y)),
                             fmaxf(fabsf(v.z), fabsf(v.w))));
    }
#pragma unroll
    for (int o = 16; o; o >>= 1) mx = fmaxf(mx, __shfl_xor_sync(~0u, mx, o));
    const float Sv = (mx > 0.0f) ? (1048576.0f / mx) : 1.0f;

    // pass 2: digits + exact residual bounds
    float sum_r = 0.0f;
    int   sum_c = 0;
    for (int i = lane * 4; i < Kpad; i += 128) {
        float w[4] = {0.f, 0.f, 0.f, 0.f};
        if (i < K) {   // K % 4 == 0
            const float4 v = *reinterpret_cast<const float4*>(W + (size_t)row * K + i);
            w[0] = v.x; w[1] = v.y; w[2] = v.z; w[3] = v.w;
        }
        char av[4], bv[4], cv[4];
#pragma unroll
        for (int j = 0; j < 4; j++) {
            int q = __float2int_rn(w[j] * Sv);
            q = max(-1048576, min(1048576, q));
            // residual |w*S - q| with single-rounding fma
            sum_r += fabsf(fmaf(w[j], Sv, (float)(-q)));
            int c = q & 127; if (c >= 64) c -= 128; q = (q - c) >> 7;
            int b = q & 127; if (b >= 64) b -= 128; q = (q - b) >> 7;
            // now |q| <= 64
            av[j] = (char)q; bv[j] = (char)b; cv[j] = (char)c;
            sum_c += abs(c);
        }
        *reinterpret_cast<char4*>(Wa + (size_t)row * Kpad + i) =
            make_char4(av[0], av[1], av[2], av[3]);
        *reinterpret_cast<char4*>(Wb + (size_t)row * Kpad + i) =
            make_char4(bv[0], bv[1], bv[2], bv[3]);
        *reinterpret_cast<char4*>(Wc + (size_t)row * Kpad + i) =
            make_char4(cv[0], cv[1], cv[2], cv[3]);
    }
#pragma unroll
    for (int o = 16; o; o >>= 1) {
        sum_r += __shfl_xor_sync(~0u, sum_r, o);
        sum_c += __shfl_xor_sync(~0u, sum_c, o);
    }
    if (lane == 0) {
        const float e3v = sum_r + 1024.0f;   // margin for fp epilogue rounding
        S[row]  = Sv;
        e3[row] = e3v;
        e2[row] = (float)sum_c + e3v;
    }
}

// ---------------- INT8 HMMA GEMM + threshold + candidate capture --------------
// Stage: A 128x128B (16KB) + Wa (16KB) + Wb (16KB) = 48KB; 4 stages = 192KB.
#define STAGE_BYTES 49152
#define NSTAGES 4
#define GEMM_SMEM_BYTES (1024 + NSTAGES * STAGE_BYTES)

__global__ __launch_bounds__(256, 1)
void spike_gemm_s8(const int8_t* __restrict__ A,
                   const int8_t* __restrict__ Ba,
                   const int8_t* __restrict__ Bb,
                   const float* __restrict__ S,
                   const float* __restrict__ e2,
                   void* __restrict__ Cout,
                   uint32_t* __restrict__ cand_rc,
                   long long* __restrict__ cand_t2,
                   uint32_t* __restrict__ cnt,
                   int Kpad, int nchunks, int Nstride, int Nstore, int out_i8) {
    extern __shared__ char smem[];
    const uint32_t sbase = smem_u32(smem);
    const uint32_t data0 = (sbase + 1023u) & ~1023u;

    const int tid  = threadIdx.x;
    const int lane = tid & 31;
    const int wid  = tid >> 5;
    const int wm   = wid & 1;           // 2 warp-rows x 64
    const int wn   = wid >> 1;          // 4 warp-cols x 32
    const int bm   = blockIdx.y * 128;
    const int bn   = blockIdx.x * 128;
    const int K16  = Kpad >> 4;         // uint4 units per row

    // ldmatrix lane addressing (b16 view of s8 data)
    const int rA = lane & 15;
    const int kA = (lane >> 4) * 16;
    const int rB = ((lane >> 4) << 3) | (lane & 7);
    const int kB = ((lane >> 3) & 1) * 16;

    int accA[4][4][4], accB[4][4][4];
#pragma unroll
    for (int mt = 0; mt < 4; mt++)
#pragma unroll
        for (int nt = 0; nt < 4; nt++)
#pragma unroll
            for (int r = 0; r < 4; r++) { accA[mt][nt][r] = 0; accB[mt][nt][r] = 0; }

    auto load_chunk = [&](int ch) {
        const uint32_t buf = data0 + (uint32_t)(ch & (NSTAGES - 1)) * STAGE_BYTES;
        const int k0u = ch << 3;        // 128 bytes = 8 uint4
#pragma unroll
        for (int t = 0; t < 4; ++t) {
            const int u = tid + t * 256;
            const int row = u >> 3, ku = u & 7;
            const uint4* src = reinterpret_cast<const uint4*>(A)
                             + (size_t)(bm + row) * K16 + k0u + ku;
            CP_ASYNC16(buf + sw128(row * 128 + ku * 16), src);
        }
#pragma unroll
        for (int t = 0; t < 4; ++t) {
            const int u = tid + t * 256;
            const int row = u >> 3, ku = u & 7;
            const uint4* src = reinterpret_cast<const uint4*>(Ba)
                             + (size_t)(bn + row) * K16 + k0u + ku;
            CP_ASYNC16(buf + 16384u + sw128(row * 128 + ku * 16), src);
        }
#pragma unroll
        for (int t = 0; t < 4; ++t) {
            const int u = tid + t * 256;
            const int row = u >> 3, ku = u & 7;
            const uint4* src = reinterpret_cast<const uint4*>(Bb)
                             + (size_t)(bn + row) * K16 + k0u + ku;
            CP_ASYNC16(buf + 32768u + sw128(row * 128 + ku * 16), src);
        }
    };

    load_chunk(0); CP_COMMIT();
    load_chunk(1); CP_COMMIT();
    load_chunk(2); CP_COMMIT();

    for (int ch = 0; ch < nchunks; ++ch) {
        CP_WAIT(2);
        __syncthreads();

        if (ch + 3 < nchunks) load_chunk(ch + 3);
        CP_COMMIT();

        const uint32_t buf = data0 + (uint32_t)(ch & (NSTAGES - 1)) * STAGE_BYTES;
#pragma unroll
        for (int ks = 0; ks < 4; ++ks) {    // 4 x k32 int8
            uint32_t a[4][4];
#pragma unroll
            for (int mt = 0; mt < 4; mt++) {
                const uint32_t addr = buf
                    + sw128((wm * 64 + mt * 16 + rA) * 128 + ks * 32 + kA);
                LDSM_X4(a[mt], addr);
            }
            // split A (digit a, weight 2^14)
            {
                uint32_t b[2][4];
#pragma unroll
                for (int nt2 = 0; nt2 < 2; nt2++) {
                    const uint32_t addr = buf + 16384u
                        + sw128((wn * 32 + nt2 * 16 + rB) * 128 + ks * 32 + kB);
                    LDSM_X4(b[nt2], addr);
                }
#pragma unroll
                for (int mt = 0; mt < 4; mt++)
#pragma unroll
                    for (int nt = 0; nt < 4; nt++)
                        MMAS8(accA[mt][nt], a[mt],
                              b[nt >> 1][(nt & 1) * 2], b[nt >> 1][(nt & 1) * 2 + 1]);
            }
            // split B (digit b, weight 2^7)
            {
                uint32_t b[2][4];
#pragma unroll
                for (int nt2 = 0; nt2 < 2; nt2++) {
                    const uint32_t addr = buf + 32768u
                        + sw128((wn * 32 + nt2 * 16 + rB) * 128 + ks * 32 + kB);
                    LDSM_X4(b[nt2], addr);
                }
#pragma unroll
                for (int mt = 0; mt < 4; mt++)
#pragma unroll
                    for (int nt = 0; nt < 4; nt++)
                        MMAS8(accB[mt][nt], a[mt],
                              b[nt >> 1][(nt & 1) * 2], b[nt >> 1][(nt & 1) * 2 + 1]);
            }
        }
    }

    // ---- epilogue ----
#pragma unroll
    for (int mt = 0; mt < 4; mt++) {
        const int row0 = bm + wm * 64 + mt * 16 + (lane >> 2);
#pragma unroll
        for (int nt = 0; nt < 4; nt++) {
            const int col = bn + wn * 32 + nt * 8 + (lane & 3) * 2;
            const float sj[2] = {S[col], S[col + 1]};
            const float ee[2] = {e2[col], e2[col + 1]};
            int sp[4];
#pragma unroll
            for (int r = 0; r < 4; r++) {
                const int Sa = accA[mt][nt][r];
                const int Sb = accB[mt][nt][r];
                const float t2f = fmaf((float)Sa, 16384.0f, (float)Sb * 128.0f);
                const float diff = t2f - sj[r & 1];
                sp[r] = (diff >= 0.0f);
                const int colr = col + (r & 1);
                if (fabsf(diff) <= ee[r & 1] && colr < Nstore) {
                    const int rowr = row0 + (r >> 1) * 8;
                    const uint32_t idx = atomicAdd(cnt, 1u);
                    if (idx < MAXC) {
                        cand_rc[idx] = ((uint32_t)rowr << 16) | (uint32_t)colr;
                        cand_t2[idx] = (((long long)Sa) << 14) + (((long long)Sb) << 7);
                    }
                }
            }
            if (out_i8) {
                int8_t* C = reinterpret_cast<int8_t*>(Cout);
                *reinterpret_cast<uint16_t*>(C + (size_t)row0 * Nstride + col) =
                    (uint16_t)(sp[0] | (sp[1] << 8));
                *reinterpret_cast<uint16_t*>(C + (size_t)(row0 + 8) * Nstride + col) =
                    (uint16_t)(sp[2] | (sp[3] << 8));
            } else if (col < Nstore) {
                float* C = reinterpret_cast<float*>(Cout);
                *reinterpret_cast<float2*>(C + (size_t)row0 * Nstride + col) =
                    make_float2((float)sp[0], (float)sp[1]);
                *reinterpret_cast<float2*>(C + (size_t)(row0 + 8) * Nstride + col) =
                    make_float2((float)sp[2], (float)sp[3]);
            }
        }
    }
}

// ---------------- fixup 1: add c-digit contribution (dp4a) --------------------
__global__ void fixc_kernel(const uint32_t* __restrict__ crc,
                            const long long* __restrict__ ct2,
                            const uint32_t* __restrict__ cntp,
                            const int8_t* __restrict__ X,
                            const int8_t* __restrict__ Wc,
                            const float* __restrict__ S,
                            const float* __restrict__ e3,
                            int Kpad, void* __restrict__ Cout,
                            int Nstride, int out_i8,
                            uint32_t* __restrict__ crc_e,
                            uint32_t* __restrict__ cnt_e) {
    const int gw   = (blockIdx.x * blockDim.x + threadIdx.x) >> 5;
    const int lane = threadIdx.x & 31;
    const int nw   = (gridDim.x * blockDim.x) >> 5;
    uint32_t n = *cntp; if (n > MAXC) n = MAXC;
    const int K16 = Kpad >> 4;
    for (uint32_t i = gw; i < n; i += nw) {
        const uint32_t e = crc[i];
        const int row = (int)(e >> 16);
        const int col = (int)(e & 0xFFFFu);
        int sc = 0;
        const uint4* xr = reinterpret_cast<const uint4*>(X)  + (size_t)row * K16;
        const uint4* cr = reinterpret_cast<const uint4*>(Wc) + (size_t)col * K16;
        for (int u = lane; u < K16; u += 32) {
            const uint4 xv = xr[u];
            const uint4 cv = cr[u];
            sc = dp4a_s(xv.x, cv.x, sc);
            sc = dp4a_s(xv.y, cv.y, sc);
            sc = dp4a_s(xv.z, cv.z, sc);
            sc = dp4a_s(xv.w, cv.w, sc);
        }
#pragma unroll
        for (int o = 16; o; o >>= 1) sc += __shfl_xor_sync(~0u, sc, o);
        if (lane == 0) {
            const long long t = ct2[i] + sc;
            const double dd = (double)t - (double)S[col];
            if (fabs(dd) <= (double)e3[col]) {
                const uint32_t idx = atomicAdd(cnt_e, 1u);
                if (idx < MAXC) crc_e[idx] = e;
            } else {
                const int spike = (dd >= 0.0);
                if (out_i8)
                    reinterpret_cast<int8_t*>(Cout)[(size_t)row * Nstride + col] =
                        (int8_t)spike;
                else
                    reinterpret_cast<float*>(Cout)[(size_t)row * Nstride + col] =
                        (float)spike;
            }
        }
    }
}

// ---------------- fixup 2: exact fp32 dot -------------------------------------
__global__ void fixe_kernel(const uint32_t* __restrict__ crc,
                            const uint32_t* __restrict__ cntp,
                            const int8_t* __restrict__ X, int Xstride,
                            const float* __restrict__ W, int K,
                            void* __restrict__ Cout, int Nstride, int out_i8) {
    const int gw   = (blockIdx.x * blockDim.x + threadIdx.x) >> 5;
    const int lane = threadIdx.x & 31;
    const int nw   = (gridDim.x * blockDim.x) >> 5;
    uint32_t n = *cntp; if (n > MAXC) n = MAXC;
    for (uint32_t i = gw; i < n; i += nw) {
        const uint32_t e = crc[i];
        const int row = (int)(e >> 16);
        const int col = (int)(e & 0xFFFFu);
        float s = 0.0f;
        for (int k = lane; k < K; k += 32)
            s += (float)X[(size_t)row * Xstride + k] * W[(size_t)col * K + k];
#pragma unroll
        for (int o = 16; o; o >>= 1) s += __shfl_xor_sync(~0u, s, o);
        if (lane == 0) {
            const int spike = (s >= 1.0f);
            if (out_i8)
                reinterpret_cast<int8_t*>(Cout)[(size_t)row * Nstride + col] =
                    (int8_t)spike;
            else
                reinterpret_cast<float*>(Cout)[(size_t)row * Nstride + col] =
                    (float)spike;
        }
    }
}

// ---------------- host launch --------------------------------------------------
extern "C" void kernel_launch(void* const* d_in, const int* in_sizes, int n_in,
                              void* d_out, int out_size) {
    const float* x  = (const float*)d_in[0];
    const float* W1 = (const float*)d_in[1];
    const float* W2 = (const float*)d_in[2];
    float* out = (float*)d_out;

    int8_t *xi, *w1a, *w1b, *w1c, *w2a, *w2b, *w2c, *s1i;
    float *S1, *e21, *e31, *S2, *e22, *e32;
    uint32_t *crc1, *crc2, *crc1e, *crc2e, *cnt;
    long long *ct1, *ct2;
    cudaGetSymbolAddress((void**)&xi,  g_xi);
    cudaGetSymbolAddress((void**)&w1a, g_w1a);
    cudaGetSymbolAddress((void**)&w1b, g_w1b);
    cudaGetSymbolAddress((void**)&w1c, g_w1c);
    cudaGetSymbolAddress((void**)&w2a, g_w2a);
    cudaGetSymbolAddress((void**)&w2b, g_w2b);
    cudaGetSymbolAddress((void**)&w2c, g_w2c);
    cudaGetSymbolAddress((void**)&s1i, g_s1i);
    cudaGetSymbolAddress((void**)&S1,  g_S1);
    cudaGetSymbolAddress((void**)&e21, g_e21);
    cudaGetSymbolAddress((void**)&e31, g_e31);
    cudaGetSymbolAddress((void**)&S2,  g_S2);
    cudaGetSymbolAddress((void**)&e22, g_e22);
    cudaGetSymbolAddress((void**)&e32, g_e32);
    cudaGetSymbolAddress((void**)&crc1,  g_crc1);
    cudaGetSymbolAddress((void**)&ct1,   g_ct1);
    cudaGetSymbolAddress((void**)&crc2,  g_crc2);
    cudaGetSymbolAddress((void**)&ct2,   g_ct2);
    cudaGetSymbolAddress((void**)&crc1e, g_crc1e);
    cudaGetSymbolAddress((void**)&crc2e, g_crc2e);
    cudaGetSymbolAddress((void**)&cnt,   g_cnt);

    cudaFuncSetAttribute(spike_gemm_s8,
                         cudaFuncAttributeMaxDynamicSharedMemorySize,
                         GEMM_SMEM_BYTES);

    reset_kernel<<<1, 32>>>();
    cvt_x_s8<<<2048, 256>>>(x, xi);
    quant_w<<<FEAT / 8, 256>>>(W1, FEAT, FEAT, IN_K, IN_KPAD,
                               w1a, w1b, w1c, S1, e21, e31);
    quant_w<<<OUT_PAD / 8, 256>>>(W2, OUT_N, OUT_PAD, FEAT, FEAT,
                                  w2a, w2b, w2c, S2, e22, e32);

    // Layer 1: s1 = (x @ W1^T >= 1)  [int8 out]
    {
        dim3 grid(FEAT / 128, B_ROWS / 128);
        spike_gemm_s8<<<grid, 256, GEMM_SMEM_BYTES>>>(
            xi, w1a, w1b, S1, e21, s1i, crc1, ct1, cnt + 0,
            IN_KPAD, IN_KPAD / 128, FEAT, FEAT, 1);
    }
    fixc_kernel<<<512, 256>>>(crc1, ct1, cnt + 0, xi, w1c, S1, e31,
                              IN_KPAD, s1i, FEAT, 1, crc1e, cnt + 1);
    fixe_kernel<<<256, 256>>>(crc1e, cnt + 1, xi, IN_KPAD, W1, IN_K,
                              s1i, FEAT, 1);

    // Layer 2: out = (s1 @ W2^T >= 1)  [fp32 out]
    {
        dim3 grid(OUT_PAD / 128, B_ROWS / 128);
        spike_gemm_s8<<<grid, 256, GEMM_SMEM_BYTES>>>(
            s1i, w2a, w2b, S2, e22, out, crc2, ct2, cnt + 2,
            FEAT, FEAT / 128, OUT_N, OUT_N, 0);
    }
    fixc_kernel<<<512, 256>>>(crc2, ct2, cnt + 2, s1i, w2c, S2, e32,
                              FEAT, out, OUT_N, 0, crc2e, cnt + 3);
    fixe_kernel<<<256, 256>>>(crc2e, cnt + 3, s1i, FEAT, W2, FEAT,
                              out, OUT_N, 0);
}

// round 8
// speedup vs baseline: 1.0041x; 1.0041x over previous
#include <cuda_runtime.h>
#include <cstdint>

// ---------------------------------------------------------------------------
// TempoJelly R7: INT8 tensor cores, exact integer accumulation, spill-free.
//   Same numerics as R6 (rel_err 0.0 proven); GEMM retiled to 512 threads /
//   16 warps of 32x32 so per-thread accumulators drop 128 -> 64 s32 regs.
//
//  - activations {0,1} -> int8 (exact)
//  - per output column j: q_k = round(w_k * S_j), |q| <= 2^20,
//    balanced base-128 digits q = a*2^14 + b*2^7 + c, a,b,c in [-64,64]
//  - GEMM (mma.m16n8k32.s8): Sa = sum x*a, Sb = sum x*b, exact s32
//  - epilogue: t2 = Sa*2^14 + Sb*2^7 vs S_j with bound eps2 -> candidates
//  - fixup1: + c-digit via dp4a; fixup2 (rare): exact fp32 dot
// ---------------------------------------------------------------------------

#define B_ROWS  4096
#define IN_K    3136
#define IN_KPAD 3200
#define FEAT    6272
#define OUT_N   500
#define OUT_PAD 512
#define MAXC    (1 << 21)

// ---------------- static scratch --------------------------------------------
__device__ __align__(16) int8_t g_xi [(size_t)B_ROWS * IN_KPAD];
__device__ __align__(16) int8_t g_w1a[(size_t)FEAT * IN_KPAD];
__device__ __align__(16) int8_t g_w1b[(size_t)FEAT * IN_KPAD];
__device__ __align__(16) int8_t g_w1c[(size_t)FEAT * IN_KPAD];
__device__ __align__(16) int8_t g_w2a[(size_t)OUT_PAD * FEAT];
__device__ __align__(16) int8_t g_w2b[(size_t)OUT_PAD * FEAT];
__device__ __align__(16) int8_t g_w2c[(size_t)OUT_PAD * FEAT];
__device__ __align__(16) int8_t g_s1i[(size_t)B_ROWS * FEAT];
__device__ float g_S1[FEAT],    g_e21[FEAT],    g_e31[FEAT];
__device__ float g_S2[OUT_PAD], g_e22[OUT_PAD], g_e32[OUT_PAD];
__device__ uint32_t  g_crc1[MAXC];
__device__ long long g_ct1 [MAXC];
__device__ uint32_t  g_crc2[MAXC];
__device__ long long g_ct2 [MAXC];
__device__ uint32_t  g_crc1e[MAXC];
__device__ uint32_t  g_crc2e[MAXC];
__device__ uint32_t  g_cnt[4];

// ---------------- helpers ----------------------------------------------------
__device__ __forceinline__ uint32_t smem_u32(const void* p) {
    return (uint32_t)__cvta_generic_to_shared(p);
}
__device__ __forceinline__ uint32_t sw128(uint32_t off) {
    return off ^ ((off >> 3) & 0x70);
}
__device__ __forceinline__ int dp4a_s(uint32_t a, uint32_t b, int c) {
    return __dp4a((int)a, (int)b, c);
}

#define CP_ASYNC16(smaddr, gptr)                                               \
    asm volatile("cp.async.cg.shared.global [%0], [%1], 16;"                   \
                 :: "r"(smaddr), "l"(gptr))
#define CP_COMMIT() asm volatile("cp.async.commit_group;" ::: "memory")
#define CP_WAIT(n)  asm volatile("cp.async.wait_group %0;" :: "n"(n) : "memory")

#define LDSM_X4(r, addr)                                                       \
    asm volatile("ldmatrix.sync.aligned.m8n8.x4.shared.b16 {%0,%1,%2,%3}, [%4];" \
                 : "=r"((r)[0]), "=r"((r)[1]), "=r"((r)[2]), "=r"((r)[3])      \
                 : "r"(addr))

#define MMAS8(cc, aa, b0, b1)                                                  \
    asm volatile("mma.sync.aligned.m16n8k32.row.col.s32.s8.s8.s32 "            \
                 "{%0,%1,%2,%3},{%4,%5,%6,%7},{%8,%9},{%0,%1,%2,%3};"          \
                 : "+r"((cc)[0]), "+r"((cc)[1]), "+r"((cc)[2]), "+r"((cc)[3])  \
                 : "r"((aa)[0]), "r"((aa)[1]), "r"((aa)[2]), "r"((aa)[3]),     \
                   "r"(b0), "r"(b1))

// ---------------- prep kernels -----------------------------------------------
__global__ void reset_kernel() {
    if (threadIdx.x < 4) g_cnt[threadIdx.x] = 0;
}

__global__ void cvt_x_s8(const float* __restrict__ x, int8_t* __restrict__ xi) {
    const size_t n4 = (size_t)B_ROWS * IN_KPAD / 4;
    size_t i = (size_t)blockIdx.x * blockDim.x + threadIdx.x;
    const size_t stride = (size_t)gridDim.x * blockDim.x;
    for (; i < n4; i += stride) {
        const int row = (int)(i / (IN_KPAD / 4));
        const int k4  = (int)(i % (IN_KPAD / 4)) * 4;
        uchar4 o = make_uchar4(0, 0, 0, 0);
        if (k4 < IN_K) {
            const float4 v = *reinterpret_cast<const float4*>(
                x + (size_t)row * IN_K + k4);
            o.x = (v.x != 0.0f); o.y = (v.y != 0.0f);
            o.z = (v.z != 0.0f); o.w = (v.w != 0.0f);
        }
        *reinterpret_cast<uchar4*>(xi + i * 4) = o;
    }
}

__global__ void quant_w(const float* __restrict__ W, int n_rows, int rows_pad,
                        int K, int Kpad,
                        int8_t* __restrict__ Wa, int8_t* __restrict__ Wb,
                        int8_t* __restrict__ Wc,
                        float* __restrict__ S, float* __restrict__ e2,
                        float* __restrict__ e3) {
    const int wid  = threadIdx.x >> 5;
    const int lane = threadIdx.x & 31;
    const int row  = blockIdx.x * (blockDim.x >> 5) + wid;
    if (row >= rows_pad) return;

    if (row >= n_rows) {
        for (int i = lane * 4; i < Kpad; i += 128) {
            *reinterpret_cast<char4*>(Wa + (size_t)row * Kpad + i) = make_char4(0,0,0,0);
            *reinterpret_cast<char4*>(Wb + (size_t)row * Kpad + i) = make_char4(0,0,0,0);
            *reinterpret_cast<char4*>(Wc + (size_t)row * Kpad + i) = make_char4(0,0,0,0);
        }
        if (lane == 0) { S[row] = 3.0e9f; e2[row] = 0.0f; e3[row] = 0.0f; }
        return;
    }

    float mx = 0.0f;
    for (int i = lane * 4; i < K; i += 128) {
        const float4 v = *reinterpret_cast<const float4*>(W + (size_t)row * K + i);
        mx = fmaxf(mx, fmaxf(fmaxf(fabsf(v.x), fabsf(v.y)),
                             fmaxf(fabsf(v.z), fabsf(v.w))));
    }
#pragma unroll
    for (int o = 16; o; o >>= 1) mx = fmaxf(mx, __shfl_xor_sync(~0u, mx, o));
    const float Sv = (mx > 0.0f) ? (1048576.0f / mx) : 1.0f;

    float sum_r = 0.0f;
    int   sum_c = 0;
    for (int i = lane * 4; i < Kpad; i += 128) {
        float w[4] = {0.f, 0.f, 0.f, 0.f};
        if (i < K) {
            const float4 v = *reinterpret_cast<const float4*>(W + (size_t)row * K + i);
            w[0] = v.x; w[1] = v.y; w[2] = v.z; w[3] = v.w;
        }
        char av[4], bv[4], cv[4];
#pragma unroll
        for (int j = 0; j < 4; j++) {
            int q = __float2int_rn(w[j] * Sv);
            q = max(-1048576, min(1048576, q));
            sum_r += fabsf(fmaf(w[j], Sv, (float)(-q)));
            int c = q & 127; if (c >= 64) c -= 128; q = (q - c) >> 7;
            int b = q & 127; if (b >= 64) b -= 128; q = (q - b) >> 7;
            av[j] = (char)q; bv[j] = (char)b; cv[j] = (char)c;
            sum_c += abs(c);
        }
        *reinterpret_cast<char4*>(Wa + (size_t)row * Kpad + i) =
            make_char4(av[0], av[1], av[2], av[3]);
        *reinterpret_cast<char4*>(Wb + (size_t)row * Kpad + i) =
            make_char4(bv[0], bv[1], bv[2], bv[3]);
        *reinterpret_cast<char4*>(Wc + (size_t)row * Kpad + i) =
            make_char4(cv[0], cv[1], cv[2], cv[3]);
    }
#pragma unroll
    for (int o = 16; o; o >>= 1) {
        sum_r += __shfl_xor_sync(~0u, sum_r, o);
        sum_c += __shfl_xor_sync(~0u, sum_c, o);
    }
    if (lane == 0) {
        const float e3v = sum_r + 1024.0f;
        S[row]  = Sv;
        e3[row] = e3v;
        e2[row] = (float)sum_c + e3v;
    }
}

// ---------------- INT8 GEMM, 512 threads, 16 warps of 32x32 -------------------
// Stage: A 128x128B (16KB) + Wa (16KB) + Wb (16KB) = 48KB; 4 stages = 192KB.
#define STAGE_BYTES 49152
#define NSTAGES 4
#define GEMM_SMEM_BYTES (1024 + NSTAGES * STAGE_BYTES)

__global__ __launch_bounds__(512, 1)
void spike_gemm_s8(const int8_t* __restrict__ A,
                   const int8_t* __restrict__ Ba,
                   const int8_t* __restrict__ Bb,
                   const float* __restrict__ S,
                   const float* __restrict__ e2,
                   void* __restrict__ Cout,
                   uint32_t* __restrict__ cand_rc,
                   long long* __restrict__ cand_t2,
                   uint32_t* __restrict__ cnt,
                   int Kpad, int nchunks, int Nstride, int Nstore, int out_i8) {
    extern __shared__ char smem[];
    const uint32_t sbase = smem_u32(smem);
    const uint32_t data0 = (sbase + 1023u) & ~1023u;

    const int tid  = threadIdx.x;
    const int lane = tid & 31;
    const int wid  = tid >> 5;
    const int wm   = wid & 3;           // 4 warp-rows x 32
    const int wn   = wid >> 2;          // 4 warp-cols x 32
    const int bm   = blockIdx.y * 128;
    const int bn   = blockIdx.x * 128;
    const int K16  = Kpad >> 4;

    const int rA = lane & 15;
    const int kA = (lane >> 4) * 16;
    const int rB = ((lane >> 4) << 3) | (lane & 7);
    const int kB = ((lane >> 3) & 1) * 16;

    int accA[2][4][4], accB[2][4][4];   // 64 s32 total
#pragma unroll
    for (int mt = 0; mt < 2; mt++)
#pragma unroll
        for (int nt = 0; nt < 4; nt++)
#pragma unroll
            for (int r = 0; r < 4; r++) { accA[mt][nt][r] = 0; accB[mt][nt][r] = 0; }

    auto load_chunk = [&](int ch) {
        const uint32_t buf = data0 + (uint32_t)(ch & (NSTAGES - 1)) * STAGE_BYTES;
        const int k0u = ch << 3;
#pragma unroll
        for (int t = 0; t < 2; ++t) {
            const int u = tid + t * 512;
            const int row = u >> 3, ku = u & 7;
            const uint4* src = reinterpret_cast<const uint4*>(A)
                             + (size_t)(bm + row) * K16 + k0u + ku;
            CP_ASYNC16(buf + sw128(row * 128 + ku * 16), src);
        }
#pragma unroll
        for (int t = 0; t < 2; ++t) {
            const int u = tid + t * 512;
            const int row = u >> 3, ku = u & 7;
            const uint4* src = reinterpret_cast<const uint4*>(Ba)
                             + (size_t)(bn + row) * K16 + k0u + ku;
            CP_ASYNC16(buf + 16384u + sw128(row * 128 + ku * 16), src);
        }
#pragma unroll
        for (int t = 0; t < 2; ++t) {
            const int u = tid + t * 512;
            const int row = u >> 3, ku = u & 7;
            const uint4* src = reinterpret_cast<const uint4*>(Bb)
                             + (size_t)(bn + row) * K16 + k0u + ku;
            CP_ASYNC16(buf + 32768u + sw128(row * 128 + ku * 16), src);
        }
    };

    load_chunk(0); CP_COMMIT();
    load_chunk(1); CP_COMMIT();
    load_chunk(2); CP_COMMIT();

    for (int ch = 0; ch < nchunks; ++ch) {
        CP_WAIT(2);
        __syncthreads();

        if (ch + 3 < nchunks) load_chunk(ch + 3);
        CP_COMMIT();

        const uint32_t buf = data0 + (uint32_t)(ch & (NSTAGES - 1)) * STAGE_BYTES;
#pragma unroll
        for (int ks = 0; ks < 4; ++ks) {
            uint32_t a[2][4];
#pragma unroll
            for (int mt = 0; mt < 2; mt++) {
                const uint32_t addr = buf
                    + sw128((wm * 32 + mt * 16 + rA) * 128 + ks * 32 + kA);
                LDSM_X4(a[mt], addr);
            }
            {   // digit a (weight 2^14)
                uint32_t b[2][4];
#pragma unroll
                for (int nt2 = 0; nt2 < 2; nt2++) {
                    const uint32_t addr = buf + 16384u
                        + sw128((wn * 32 + nt2 * 16 + rB) * 128 + ks * 32 + kB);
                    LDSM_X4(b[nt2], addr);
                }
#pragma unroll
                for (int mt = 0; mt < 2; mt++)
#pragma unroll
                    for (int nt = 0; nt < 4; nt++)
                        MMAS8(accA[mt][nt], a[mt],
                              b[nt >> 1][(nt & 1) * 2], b[nt >> 1][(nt & 1) * 2 + 1]);
            }
            {   // digit b (weight 2^7)
                uint32_t b[2][4];
#pragma unroll
                for (int nt2 = 0; nt2 < 2; nt2++) {
                    const uint32_t addr = buf + 32768u
                        + sw128((wn * 32 + nt2 * 16 + rB) * 128 + ks * 32 + kB);
                    LDSM_X4(b[nt2], addr);
                }
#pragma unroll
                for (int mt = 0; mt < 2; mt++)
#pragma unroll
                    for (int nt = 0; nt < 4; nt++)
                        MMAS8(accB[mt][nt], a[mt],
                              b[nt >> 1][(nt & 1) * 2], b[nt >> 1][(nt & 1) * 2 + 1]);
            }
        }
    }

    // ---- epilogue ----
#pragma unroll
    for (int mt = 0; mt < 2; mt++) {
        const int row0 = bm + wm * 32 + mt * 16 + (lane >> 2);
#pragma unroll
        for (int nt = 0; nt < 4; nt++) {
            const int col = bn + wn * 32 + nt * 8 + (lane & 3) * 2;
            const float sj[2] = {S[col], S[col + 1]};
            const float ee[2] = {e2[col], e2[col + 1]};
            int sp[4];
#pragma unroll
            for (int r = 0; r < 4; r++) {
                const int Sa = accA[mt][nt][r];
                const int Sb = accB[mt][nt][r];
                const float t2f = fmaf((float)Sa, 16384.0f, (float)Sb * 128.0f);
                const float diff = t2f - sj[r & 1];
                sp[r] = (diff >= 0.0f);
                const int colr = col + (r & 1);
                if (fabsf(diff) <= ee[r & 1] && colr < Nstore) {
                    const int rowr = row0 + (r >> 1) * 8;
                    const uint32_t idx = atomicAdd(cnt, 1u);
                    if (idx < MAXC) {
                        cand_rc[idx] = ((uint32_t)rowr << 16) | (uint32_t)colr;
                        cand_t2[idx] = (((long long)Sa) << 14) + (((long long)Sb) << 7);
                    }
                }
            }
            if (out_i8) {
                int8_t* C = reinterpret_cast<int8_t*>(Cout);
                *reinterpret_cast<uint16_t*>(C + (size_t)row0 * Nstride + col) =
                    (uint16_t)(sp[0] | (sp[1] << 8));
                *reinterpret_cast<uint16_t*>(C + (size_t)(row0 + 8) * Nstride + col) =
                    (uint16_t)(sp[2] | (sp[3] << 8));
            } else if (col < Nstore) {
                float* C = reinterpret_cast<float*>(Cout);
                *reinterpret_cast<float2*>(C + (size_t)row0 * Nstride + col) =
                    make_float2((float)sp[0], (float)sp[1]);
                *reinterpret_cast<float2*>(C + (size_t)(row0 + 8) * Nstride + col) =
                    make_float2((float)sp[2], (float)sp[3]);
            }
        }
    }
}

// ---------------- fixup 1: add c-digit via dp4a -------------------------------
__global__ void fixc_kernel(const uint32_t* __restrict__ crc,
                            const long long* __restrict__ ct2,
                            const uint32_t* __restrict__ cntp,
                            const int8_t* __restrict__ X,
                            const int8_t* __restrict__ Wc,
                            const float* __restrict__ S,
                            const float* __restrict__ e3,
                            int Kpad, void* __restrict__ Cout,
                            int Nstride, int out_i8,
                            uint32_t* __restrict__ crc_e,
                            uint32_t* __restrict__ cnt_e) {
    const int gw   = (blockIdx.x * blockDim.x + threadIdx.x) >> 5;
    const int lane = threadIdx.x & 31;
    const int nw   = (gridDim.x * blockDim.x) >> 5;
    uint32_t n = *cntp; if (n > MAXC) n = MAXC;
    const int K16 = Kpad >> 4;
    for (uint32_t i = gw; i < n; i += nw) {
        const uint32_t e = crc[i];
        const int row = (int)(e >> 16);
        const int col = (int)(e & 0xFFFFu);
        int sc = 0;
        const uint4* xr = reinterpret_cast<const uint4*>(X)  + (size_t)row * K16;
        const uint4* cr = reinterpret_cast<const uint4*>(Wc) + (size_t)col * K16;
        for (int u = lane; u < K16; u += 32) {
            const uint4 xv = xr[u];
            const uint4 cv = cr[u];
            sc = dp4a_s(xv.x, cv.x, sc);
            sc = dp4a_s(xv.y, cv.y, sc);
            sc = dp4a_s(xv.z, cv.z, sc);
            sc = dp4a_s(xv.w, cv.w, sc);
        }
#pragma unroll
        for (int o = 16; o; o >>= 1) sc += __shfl_xor_sync(~0u, sc, o);
        if (lane == 0) {
            const long long t = ct2[i] + sc;
            const double dd = (double)t - (double)S[col];
            if (fabs(dd) <= (double)e3[col]) {
                const uint32_t idx = atomicAdd(cnt_e, 1u);
                if (idx < MAXC) crc_e[idx] = e;
            } else {
                const int spike = (dd >= 0.0);
                if (out_i8)
                    reinterpret_cast<int8_t*>(Cout)[(size_t)row * Nstride + col] =
                        (int8_t)spike;
                else
                    reinterpret_cast<float*>(Cout)[(size_t)row * Nstride + col] =
                        (float)spike;
            }
        }
    }
}

// ---------------- fixup 2: exact fp32 dot -------------------------------------
__global__ void fixe_kernel(const uint32_t* __restrict__ crc,
                            const uint32_t* __restrict__ cntp,
                            const int8_t* __restrict__ X, int Xstride,
                            const float* __restrict__ W, int K,
                            void* __restrict__ Cout, int Nstride, int out_i8) {
    const int gw   = (blockIdx.x * blockDim.x + threadIdx.x) >> 5;
    const int lane = threadIdx.x & 31;
    const int nw   = (gridDim.x * blockDim.x) >> 5;
    uint32_t n = *cntp; if (n > MAXC) n = MAXC;
    for (uint32_t i = gw; i < n; i += nw) {
        const uint32_t e = crc[i];
        const int row = (int)(e >> 16);
        const int col = (int)(e & 0xFFFFu);
        float s = 0.0f;
        for (int k = lane; k < K; k += 32)
            s += (float)X[(size_t)row * Xstride + k] * W[(size_t)col * K + k];
#pragma unroll
        for (int o = 16; o; o >>= 1) s += __shfl_xor_sync(~0u, s, o);
        if (lane == 0) {
            const int spike = (s >= 1.0f);
            if (out_i8)
                reinterpret_cast<int8_t*>(Cout)[(size_t)row * Nstride + col] =
                    (int8_t)spike;
            else
                reinterpret_cast<float*>(Cout)[(size_t)row * Nstride + col] =
                    (float)spike;
        }
    }
}

// ---------------- host launch --------------------------------------------------
extern "C" void kernel_launch(void* const* d_in, const int* in_sizes, int n_in,
                              void* d_out, int out_size) {
    const float* x  = (const float*)d_in[0];
    const float* W1 = (const float*)d_in[1];
    const float* W2 = (const float*)d_in[2];
    float* out = (float*)d_out;

    int8_t *xi, *w1a, *w1b, *w1c, *w2a, *w2b, *w2c, *s1i;
    float *S1, *e21, *e31, *S2, *e22, *e32;
    uint32_t *crc1, *crc2, *crc1e, *crc2e, *cnt;
    long long *ct1, *ct2;
    cudaGetSymbolAddress((void**)&xi,  g_xi);
    cudaGetSymbolAddress((void**)&w1a, g_w1a);
    cudaGetSymbolAddress((void**)&w1b, g_w1b);
    cudaGetSymbolAddress((void**)&w1c, g_w1c);
    cudaGetSymbolAddress((void**)&w2a, g_w2a);
    cudaGetSymbolAddress((void**)&w2b, g_w2b);
    cudaGetSymbolAddress((void**)&w2c, g_w2c);
    cudaGetSymbolAddress((void**)&s1i, g_s1i);
    cudaGetSymbolAddress((void**)&S1,  g_S1);
    cudaGetSymbolAddress((void**)&e21, g_e21);
    cudaGetSymbolAddress((void**)&e31, g_e31);
    cudaGetSymbolAddress((void**)&S2,  g_S2);
    cudaGetSymbolAddress((void**)&e22, g_e22);
    cudaGetSymbolAddress((void**)&e32, g_e32);
    cudaGetSymbolAddress((void**)&crc1,  g_crc1);
    cudaGetSymbolAddress((void**)&ct1,   g_ct1);
    cudaGetSymbolAddress((void**)&crc2,  g_crc2);
    cudaGetSymbolAddress((void**)&ct2,   g_ct2);
    cudaGetSymbolAddress((void**)&crc1e, g_crc1e);
    cudaGetSymbolAddress((void**)&crc2e, g_crc2e);
    cudaGetSymbolAddress((void**)&cnt,   g_cnt);

    cudaFuncSetAttribute(spike_gemm_s8,
                         cudaFuncAttributeMaxDynamicSharedMemorySize,
                         GEMM_SMEM_BYTES);

    reset_kernel<<<1, 32>>>();
    cvt_x_s8<<<2048, 256>>>(x, xi);
    quant_w<<<FEAT / 8, 256>>>(W1, FEAT, FEAT, IN_K, IN_KPAD,
                               w1a, w1b, w1c, S1, e21, e31);
    quant_w<<<OUT_PAD / 8, 256>>>(W2, OUT_N, OUT_PAD, FEAT, FEAT,
                                  w2a, w2b, w2c, S2, e22, e32);

    // Layer 1: s1 = (x @ W1^T >= 1)  [int8 out]
    {
        dim3 grid(FEAT / 128, B_ROWS / 128);
        spike_gemm_s8<<<grid, 512, GEMM_SMEM_BYTES>>>(
            xi, w1a, w1b, S1, e21, s1i, crc1, ct1, cnt + 0,
            IN_KPAD, IN_KPAD / 128, FEAT, FEAT, 1);
    }
    fixc_kernel<<<512, 256>>>(crc1, ct1, cnt + 0, xi, w1c, S1, e31,
                              IN_KPAD, s1i, FEAT, 1, crc1e, cnt + 1);
    fixe_kernel<<<256, 256>>>(crc1e, cnt + 1, xi, IN_KPAD, W1, IN_K,
                              s1i, FEAT, 1);

    // Layer 2: out = (s1 @ W2^T >= 1)  [fp32 out]
    {
        dim3 grid(OUT_PAD / 128, B_ROWS / 128);
        spike_gemm_s8<<<grid, 512, GEMM_SMEM_BYTES>>>(
            s1i, w2a, w2b, S2, e22, out, crc2, ct2, cnt + 2,
            FEAT, FEAT / 128, OUT_N, OUT_N, 0);
    }
    fixc_kernel<<<512, 256>>>(crc2, ct2, cnt + 2, s1i, w2c, S2, e32,
                              FEAT, out, OUT_N, 0, crc2e, cnt + 3);
    fixe_kernel<<<256, 256>>>(crc2e, cnt + 3, s1i, FEAT, W2, FEAT,
                              out, OUT_N, 0);
}

// round 9
// speedup vs baseline: 3.8341x; 3.8182x over previous
#include <cuda_runtime.h>
#include <cuda_fp16.h>
#include <cuda_bf16.h>
#include <cstdint>

// ---------------------------------------------------------------------------
// TempoJelly R9: single-split fp16 HMMA GEMM + bounded candidate fixup.
//   s2 = ((x @ W1^T >= 1) @ W2^T >= 1), x binary.
//
//  - x, s1 in {0,1}: exact in fp16 (GEMM operand) and int8 (fixup dots)
//  - weights: hi = fp16(w)  [one GEMM split only!]
//             mid = bf16(w - hi)  [used only in candidate fixup]
//  - eps1_col = sum|w - hi| + MARGIN: elements with |acc-1| > eps1 are
//    provably on the correct side. ~0.36% are candidates.
//  - fixup1: t = acc + sum x*mid (warp dot, int8 x * bf16 mid)
//    eps2_col = sum|w - hi - mid| + MARGIN  (~3e-4, fp32-acc margin floor)
//  - fixup2 (rare, ~3k): exact fp32 dot against original W.
//  GEMM: mma.m16n8k16.f32.f16.f16.f32, CTA 128x128, 128 thr, 4 warps of
//  64x64, BK=64, 3-stage cp.async, 2 CTAs/SM.
// ---------------------------------------------------------------------------

#define B_ROWS  4096
#define IN_K    3136
#define FEAT    6272
#define OUT_N   500
#define OUT_PAD 512
#define MAXC    (1 << 21)
#define MARGIN  3.0e-4f

// ---------------- static scratch --------------------------------------------
__device__ __align__(16) __half         g_xh  [(size_t)B_ROWS * IN_K];
__device__ __align__(16) int8_t         g_xi  [(size_t)B_ROWS * IN_K];
__device__ __align__(16) __half         g_w1h [(size_t)FEAT * IN_K];
__device__ __align__(16) __nv_bfloat16  g_w1m [(size_t)FEAT * IN_K];
__device__ __align__(16) __half         g_w2h [(size_t)OUT_PAD * FEAT];
__device__ __align__(16) __nv_bfloat16  g_w2m [(size_t)OUT_PAD * FEAT];
__device__ __align__(16) __half         g_s1h [(size_t)B_ROWS * FEAT];
__device__ __align__(16) int8_t         g_s1i [(size_t)B_ROWS * FEAT];
__device__ float g_e1a[FEAT],    g_e2a[FEAT];
__device__ float g_e1b[OUT_PAD], g_e2b[OUT_PAD];
__device__ uint32_t g_crc1[MAXC];
__device__ float    g_cv1 [MAXC];
__device__ uint32_t g_crc2[MAXC];
__device__ float    g_cv2 [MAXC];
__device__ uint32_t g_crc1e[MAXC];
__device__ uint32_t g_crc2e[MAXC];
__device__ uint32_t g_cnt[4];   // L1 cands, L1 final, L2 cands, L2 final

// ---------------- helpers ----------------------------------------------------
__device__ __forceinline__ uint32_t smem_u32(const void* p) {
    return (uint32_t)__cvta_generic_to_shared(p);
}
__device__ __forceinline__ uint32_t sw128(uint32_t off) {
    return off ^ ((off >> 3) & 0x70);
}

#define CP_ASYNC16(smaddr, gptr)                                               \
    asm volatile("cp.async.cg.shared.global [%0], [%1], 16;"                   \
                 :: "r"(smaddr), "l"(gptr))
#define CP_COMMIT() asm volatile("cp.async.commit_group;" ::: "memory")
#define CP_WAIT(n)  asm volatile("cp.async.wait_group %0;" :: "n"(n) : "memory")

#define LDSM_X4(r, addr)                                                       \
    asm volatile("ldmatrix.sync.aligned.m8n8.x4.shared.b16 {%0,%1,%2,%3}, [%4];" \
                 : "=r"((r)[0]), "=r"((r)[1]), "=r"((r)[2]), "=r"((r)[3])      \
                 : "r"(addr))

#define MMAF16(cc, aa, b0, b1)                                                 \
    asm volatile("mma.sync.aligned.m16n8k16.row.col.f32.f16.f16.f32 "          \
                 "{%0,%1,%2,%3},{%4,%5,%6,%7},{%8,%9},{%0,%1,%2,%3};"          \
                 : "+f"((cc)[0]), "+f"((cc)[1]), "+f"((cc)[2]), "+f"((cc)[3])  \
                 : "r"((aa)[0]), "r"((aa)[1]), "r"((aa)[2]), "r"((aa)[3]),     \
                   "r"(b0), "r"(b1))

// ---------------- prep kernels -----------------------------------------------
__global__ void reset_kernel() {
    if (threadIdx.x < 4) g_cnt[threadIdx.x] = 0;
}

// x (fp32 0/1) -> fp16 (GEMM) + int8 (fixup dots)
__global__ void cvt_x_kernel(const float* __restrict__ x,
                             __half* __restrict__ xh,
                             int8_t* __restrict__ xi) {
    const size_t n4 = (size_t)B_ROWS * IN_K / 4;
    size_t i = (size_t)blockIdx.x * blockDim.x + threadIdx.x;
    const size_t stride = (size_t)gridDim.x * blockDim.x;
    for (; i < n4; i += stride) {
        const float4 v = reinterpret_cast<const float4*>(x)[i];
        const int b0 = (v.x != 0.0f), b1 = (v.y != 0.0f);
        const int b2 = (v.z != 0.0f), b3 = (v.w != 0.0f);
        // fp16 1.0 = 0x3C00
        const uint32_t h01 = (b0 ? 0x3C00u : 0u) | ((b1 ? 0x3C00u : 0u) << 16);
        const uint32_t h23 = (b2 ? 0x3C00u : 0u) | ((b3 ? 0x3C00u : 0u) << 16);
        reinterpret_cast<uint2*>(xh)[i] = make_uint2(h01, h23);
        reinterpret_cast<uchar4*>(xi)[i] =
            make_uchar4((unsigned char)b0, (unsigned char)b1,
                        (unsigned char)b2, (unsigned char)b3);
    }
}

// One warp per output column: hi=fp16(w), mid=bf16(w-hi), residual bounds.
__global__ void split_w_kernel(const float* __restrict__ W, int n_rows,
                               int rows_pad, int K,
                               __half* __restrict__ Wh,
                               __nv_bfloat16* __restrict__ Wm,
                               float* __restrict__ e1,
                               float* __restrict__ e2) {
    const int wid  = threadIdx.x >> 5;
    const int lane = threadIdx.x & 31;
    const int row  = blockIdx.x * (blockDim.x >> 5) + wid;
    if (row >= rows_pad) return;

    if (row >= n_rows) {   // pad row: zeros, never a candidate
        for (int i = lane * 4; i < K; i += 128) {
            *reinterpret_cast<uint2*>(Wh + (size_t)row * K + i) = make_uint2(0, 0);
            *reinterpret_cast<uint2*>(Wm + (size_t)row * K + i) = make_uint2(0, 0);
        }
        if (lane == 0) { e1[row] = -1.0f; e2[row] = -1.0f; }
        return;
    }

    float s1 = 0.0f, s2 = 0.0f;
    for (int i = lane * 4; i < K; i += 128) {
        const float4 v = *reinterpret_cast<const float4*>(W + (size_t)row * K + i);
        const float w[4] = {v.x, v.y, v.z, v.w};
        ushort hh[4], mm[4];
#pragma unroll
        for (int j = 0; j < 4; j++) {
            const __half h = __float2half_rn(w[j]);
            const float r = w[j] - __half2float(h);
            const __nv_bfloat16 m = __float2bfloat16_rn(r);
            const float r2 = r - __bfloat162float(m);
            s1 += fabsf(r);
            s2 += fabsf(r2);
            hh[j] = __half_as_ushort(h);
            mm[j] = __bfloat16_as_ushort(m);
        }
        *reinterpret_cast<uint2*>(Wh + (size_t)row * K + i) = make_uint2(
            (uint32_t)hh[0] | ((uint32_t)hh[1] << 16),
            (uint32_t)hh[2] | ((uint32_t)hh[3] << 16));
        *reinterpret_cast<uint2*>(Wm + (size_t)row * K + i) = make_uint2(
            (uint32_t)mm[0] | ((uint32_t)mm[1] << 16),
            (uint32_t)mm[2] | ((uint32_t)mm[3] << 16));
    }
#pragma unroll
    for (int o = 16; o; o >>= 1) {
        s1 += __shfl_xor_sync(~0u, s1, o);
        s2 += __shfl_xor_sync(~0u, s2, o);
    }
    if (lane == 0) {
        e1[row] = s1 + MARGIN;
        e2[row] = s2 + MARGIN;
    }
}

// ---------------- fp16 HMMA GEMM: CTA 128x128, 4 warps of 64x64 ---------------
#define STAGE_BYTES 32768
#define NSTAGES 3
#define GEMM_SMEM_BYTES (1024 + NSTAGES * STAGE_BYTES)   // 99328 -> 2 CTAs/SM

__global__ __launch_bounds__(128, 2)
void spike_gemm_f16(const __half* __restrict__ A,
                    const __half* __restrict__ B,
                    const float* __restrict__ eps1,
                    __half* __restrict__ outH,       // dual-mode (layer 1)
                    int8_t* __restrict__ outI,
                    float* __restrict__ outF,        // fp32-mode (layer 2)
                    uint32_t* __restrict__ cand_rc,
                    float* __restrict__ cand_val,
                    uint32_t* __restrict__ cnt,
                    int K, int Nstride, int Nstore) {
    extern __shared__ char smem[];
    const uint32_t sbase = smem_u32(smem);
    const uint32_t data0 = (sbase + 1023u) & ~1023u;

    const int tid  = threadIdx.x;
    const int lane = tid & 31;
    const int wid  = tid >> 5;
    const int wm   = wid & 1;           // 2 warp-rows x 64
    const int wn   = wid >> 1;          // 2 warp-cols x 64
    const int bm   = blockIdx.y * 128;
    const int bn   = blockIdx.x * 128;
    const int K8   = K >> 3;            // uint4 units per row
    const int nchunks = K >> 6;         // BK = 64 fp16 = 128B rows

    const int rA = lane & 15;
    const int kA = (lane >> 4) * 16;
    const int rB = ((lane >> 4) << 3) | (lane & 7);
    const int kB = ((lane >> 3) & 1) * 16;

    float acc[4][4][8];                  // mt x nb(16 cols) x (2 n8 * 4)
#pragma unroll
    for (int mt = 0; mt < 4; mt++)
#pragma unroll
        for (int nb = 0; nb < 4; nb++)
#pragma unroll
            for (int r = 0; r < 8; r++) acc[mt][nb][r] = 0.0f;

    auto load_chunk = [&](int ch) {
        uint32_t buf = data0 + (uint32_t)(ch % NSTAGES) * STAGE_BYTES;
        const int k0u = ch << 3;
#pragma unroll
        for (int t = 0; t < 8; ++t) {
            const int u = tid + t * 128;
            const int row = u >> 3, ku = u & 7;
            const uint4* src = reinterpret_cast<const uint4*>(A)
                             + (size_t)(bm + row) * K8 + k0u + ku;
            CP_ASYNC16(buf + sw128(row * 128 + ku * 16), src);
        }
#pragma unroll
        for (int t = 0; t < 8; ++t) {
            const int u = tid + t * 128;
            const int row = u >> 3, ku = u & 7;
            const uint4* src = reinterpret_cast<const uint4*>(B)
                             + (size_t)(bn + row) * K8 + k0u + ku;
            CP_ASYNC16(buf + 16384u + sw128(row * 128 + ku * 16), src);
        }
        CP_COMMIT();
    };

    load_chunk(0);
    load_chunk(1);

    for (int ch = 0; ch < nchunks; ++ch) {
        CP_WAIT(1);
        __syncthreads();

        if (ch + 2 < nchunks) load_chunk(ch + 2);
        else CP_COMMIT();                 // keep group count exact in tail

        const uint32_t buf = data0 + (uint32_t)(ch % NSTAGES) * STAGE_BYTES;
#pragma unroll
        for (int ks = 0; ks < 4; ++ks) {
            uint32_t a[4][4];
#pragma unroll
            for (int mt = 0; mt < 4; mt++) {
                const uint32_t addr = buf
                    + sw128((wm * 64 + mt * 16 + rA) * 128 + ks * 32 + kA);
                LDSM_X4(a[mt], addr);
            }
#pragma unroll
            for (int nb = 0; nb < 4; nb++) {
                uint32_t b[4];
                const uint32_t addr = buf + 16384u
                    + sw128((wn * 64 + nb * 16 + rB) * 128 + ks * 32 + kB);
                LDSM_X4(b, addr);
#pragma unroll
                for (int mt = 0; mt < 4; mt++) {
                    MMAF16(acc[mt][nb] + 0, a[mt], b[0], b[1]);
                    MMAF16(acc[mt][nb] + 4, a[mt], b[2], b[3]);
                }
            }
        }
    }

    // ---- epilogue: threshold + candidate capture (with acc value) ----
    float ev[4][2][2];
#pragma unroll
    for (int nb = 0; nb < 4; nb++)
#pragma unroll
        for (int h = 0; h < 2; h++) {
            const int col = bn + wn * 64 + nb * 16 + h * 8 + (lane & 3) * 2;
            ev[nb][h][0] = eps1[col];
            ev[nb][h][1] = eps1[col + 1];
        }

#pragma unroll
    for (int mt = 0; mt < 4; mt++) {
        const int row0 = bm + wm * 64 + mt * 16 + (lane >> 2);
#pragma unroll
        for (int nb = 0; nb < 4; nb++) {
#pragma unroll
            for (int h = 0; h < 2; h++) {
                const int col = bn + wn * 64 + nb * 16 + h * 8 + (lane & 3) * 2;
                const float* v = acc[mt][nb] + h * 4;
                int sp[4];
#pragma unroll
                for (int r = 0; r < 4; r++) {
                    sp[r] = (v[r] >= 1.0f);
                    const int colr = col + (r & 1);
                    if (fabsf(v[r] - 1.0f) <= ev[nb][h][r & 1] && colr < Nstore) {
                        const int rowr = row0 + (r >> 1) * 8;
                        const uint32_t idx = atomicAdd(cnt, 1u);
                        if (idx < MAXC) {
                            cand_rc[idx]  = ((uint32_t)rowr << 16) | (uint32_t)colr;
                            cand_val[idx] = v[r];
                        }
                    }
                }
                if (outF == nullptr) {    // dual fp16 + int8 (layer 1)
                    *reinterpret_cast<uint32_t*>(
                        outH + (size_t)row0 * Nstride + col) =
                        (sp[0] ? 0x3C00u : 0u) | ((sp[1] ? 0x3C00u : 0u) << 16);
                    *reinterpret_cast<uint32_t*>(
                        outH + (size_t)(row0 + 8) * Nstride + col) =
                        (sp[2] ? 0x3C00u : 0u) | ((sp[3] ? 0x3C00u : 0u) << 16);
                    *reinterpret_cast<uint16_t*>(
                        outI + (size_t)row0 * Nstride + col) =
                        (uint16_t)(sp[0] | (sp[1] << 8));
                    *reinterpret_cast<uint16_t*>(
                        outI + (size_t)(row0 + 8) * Nstride + col) =
                        (uint16_t)(sp[2] | (sp[3] << 8));
                } else if (col < Nstore) {  // fp32 (layer 2); 500 even -> pair-safe
                    *reinterpret_cast<float2*>(
                        outF + (size_t)row0 * Nstore + col) =
                        make_float2((float)sp[0], (float)sp[1]);
                    *reinterpret_cast<float2*>(
                        outF + (size_t)(row0 + 8) * Nstore + col) =
                        make_float2((float)sp[2], (float)sp[3]);
                }
            }
        }
    }
}

// ---------------- fixup 1: add mid-residual dot (int8 x * bf16 mid) ----------
__global__ void fixmid_kernel(const uint32_t* __restrict__ crc,
                              const float* __restrict__ cval,
                              const uint32_t* __restrict__ cntp,
                              const int8_t* __restrict__ X,
                              const __nv_bfloat16* __restrict__ Wm,
                              const float* __restrict__ e2,
                              int K,
                              __half* __restrict__ outH,
                              int8_t* __restrict__ outI,
                              float* __restrict__ outF,
                              int NstrideH, int NstrideF,
                              uint32_t* __restrict__ crc_e,
                              uint32_t* __restrict__ cnt_e) {
    const int gw   = (blockIdx.x * blockDim.x + threadIdx.x) >> 5;
    const int lane = threadIdx.x & 31;
    const int nw   = (gridDim.x * blockDim.x) >> 5;
    uint32_t n = *cntp; if (n > MAXC) n = MAXC;
    for (uint32_t i = gw; i < n; i += nw) {
        const uint32_t e = crc[i];
        const int row = (int)(e >> 16);
        const int col = (int)(e & 0xFFFFu);
        float dot = 0.0f;
        const int8_t* xr = X + (size_t)row * K;
        const __nv_bfloat16* mr = Wm + (size_t)col * K;
        for (int k = lane * 4; k < K; k += 128) {
            const char4 xv = *reinterpret_cast<const char4*>(xr + k);
            const uint2 mv = *reinterpret_cast<const uint2*>(mr + k);
            const float m0 = __bfloat162float(__ushort_as_bfloat16((ushort)(mv.x & 0xFFFF)));
            const float m1 = __bfloat162float(__ushort_as_bfloat16((ushort)(mv.x >> 16)));
            const float m2 = __bfloat162float(__ushort_as_bfloat16((ushort)(mv.y & 0xFFFF)));
            const float m3 = __bfloat162float(__ushort_as_bfloat16((ushort)(mv.y >> 16)));
            dot += xv.x * m0 + xv.y * m1 + xv.z * m2 + xv.w * m3;
        }
#pragma unroll
        for (int o = 16; o; o >>= 1) dot += __shfl_xor_sync(~0u, dot, o);
        if (lane == 0) {
            const float t = cval[i] + dot;
            if (fabsf(t - 1.0f) <= e2[col]) {
                const uint32_t idx = atomicAdd(cnt_e, 1u);
                if (idx < MAXC) crc_e[idx] = e;
            } else {
                const int spike = (t >= 1.0f);
                if (outF == nullptr) {
                    outH[(size_t)row * NstrideH + col] =
                        __ushort_as_half(spike ? (ushort)0x3C00 : (ushort)0);
                    outI[(size_t)row * NstrideH + col] = (int8_t)spike;
                } else {
                    outF[(size_t)row * NstrideF + col] = (float)spike;
                }
            }
        }
    }
}

// ---------------- fixup 2: exact fp32 dot -------------------------------------
__global__ void fixe_kernel(const uint32_t* __restrict__ crc,
                            const uint32_t* __restrict__ cntp,
                            const int8_t* __restrict__ X,
                            const float* __restrict__ W, int K,
                            __half* __restrict__ outH,
                            int8_t* __restrict__ outI,
                            float* __restrict__ outF,
                            int NstrideH, int NstrideF) {
    const int gw   = (blockIdx.x * blockDim.x + threadIdx.x) >> 5;
    const int lane = threadIdx.x & 31;
    const int nw   = (gridDim.x * blockDim.x) >> 5;
    uint32_t n = *cntp; if (n > MAXC) n = MAXC;
    for (uint32_t i = gw; i < n; i += nw) {
        const uint32_t e = crc[i];
        const int row = (int)(e >> 16);
        const int col = (int)(e & 0xFFFFu);
        float s = 0.0f;
        for (int k = lane; k < K; k += 32)
            s += (float)X[(size_t)row * K + k] * W[(size_t)col * K + k];
#pragma unroll
        for (int o = 16; o; o >>= 1) s += __shfl_xor_sync(~0u, s, o);
        if (lane == 0) {
            const int spike = (s >= 1.0f);
            if (outF == nullptr) {
                outH[(size_t)row * NstrideH + col] =
                    __ushort_as_half(spike ? (ushort)0x3C00 : (ushort)0);
                outI[(size_t)row * NstrideH + col] = (int8_t)spike;
            } else {
                outF[(size_t)row * NstrideF + col] = (float)spike;
            }
        }
    }
}

// ---------------- host launch --------------------------------------------------
extern "C" void kernel_launch(void* const* d_in, const int* in_sizes, int n_in,
                              void* d_out, int out_size) {
    const float* x  = (const float*)d_in[0];
    const float* W1 = (const float*)d_in[1];
    const float* W2 = (const float*)d_in[2];
    float* out = (float*)d_out;

    __half *xh, *w1h, *w2h, *s1h;
    __nv_bfloat16 *w1m, *w2m;
    int8_t *xi, *s1i;
    float *e1a, *e2a, *e1b, *e2b, *cv1, *cv2;
    uint32_t *crc1, *crc2, *crc1e, *crc2e, *cnt;
    cudaGetSymbolAddress((void**)&xh,  g_xh);
    cudaGetSymbolAddress((void**)&xi,  g_xi);
    cudaGetSymbolAddress((void**)&w1h, g_w1h);
    cudaGetSymbolAddress((void**)&w1m, g_w1m);
    cudaGetSymbolAddress((void**)&w2h, g_w2h);
    cudaGetSymbolAddress((void**)&w2m, g_w2m);
    cudaGetSymbolAddress((void**)&s1h, g_s1h);
    cudaGetSymbolAddress((void**)&s1i, g_s1i);
    cudaGetSymbolAddress((void**)&e1a, g_e1a);
    cudaGetSymbolAddress((void**)&e2a, g_e2a);
    cudaGetSymbolAddress((void**)&e1b, g_e1b);
    cudaGetSymbolAddress((void**)&e2b, g_e2b);
    cudaGetSymbolAddress((void**)&crc1,  g_crc1);
    cudaGetSymbolAddress((void**)&cv1,   g_cv1);
    cudaGetSymbolAddress((void**)&crc2,  g_crc2);
    cudaGetSymbolAddress((void**)&cv2,   g_cv2);
    cudaGetSymbolAddress((void**)&crc1e, g_crc1e);
    cudaGetSymbolAddress((void**)&crc2e, g_crc2e);
    cudaGetSymbolAddress((void**)&cnt,   g_cnt);

    cudaFuncSetAttribute(spike_gemm_f16,
                         cudaFuncAttributeMaxDynamicSharedMemorySize,
                         GEMM_SMEM_BYTES);

    reset_kernel<<<1, 32>>>();
    cvt_x_kernel<<<2048, 256>>>(x, xh, xi);
    split_w_kernel<<<FEAT / 8, 256>>>(W1, FEAT, FEAT, IN_K, w1h, w1m, e1a, e2a);
    split_w_kernel<<<OUT_PAD / 8, 256>>>(W2, OUT_N, OUT_PAD, FEAT,
                                         w2h, w2m, e1b, e2b);

    // Layer 1: s1 = (x @ W1^T >= 1)  -> dual fp16 + int8
    {
        dim3 grid(FEAT / 128, B_ROWS / 128);   // (49, 32)
        spike_gemm_f16<<<grid, 128, GEMM_SMEM_BYTES>>>(
            xh, w1h, e1a, s1h, s1i, nullptr,
            crc1, cv1, cnt + 0, IN_K, FEAT, FEAT);
    }
    fixmid_kernel<<<512, 256>>>(crc1, cv1, cnt + 0, xi, w1m, e2a, IN_K,
                                s1h, s1i, nullptr, FEAT, 0, crc1e, cnt + 1);
    fixe_kernel<<<256, 256>>>(crc1e, cnt + 1, xi, W1, IN_K,
                              s1h, s1i, nullptr, FEAT, 0);

    // Layer 2: out = (s1 @ W2^T >= 1)  -> fp32
    {
        dim3 grid(OUT_PAD / 128, B_ROWS / 128);  // (4, 32)
        spike_gemm_f16<<<grid, 128, GEMM_SMEM_BYTES>>>(
            s1h, w2h, e1b, nullptr, nullptr, out,
            crc2, cv2, cnt + 2, FEAT, OUT_N, OUT_N);
    }
    fixmid_kernel<<<512, 256>>>(crc2, cv2, cnt + 2, s1i, w2m, e2b, FEAT,
                                nullptr, nullptr, out, 0, OUT_N, crc2e, cnt + 3);
    fixe_kernel<<<256, 256>>>(crc2e, cnt + 3, s1i, W2, FEAT,
                              nullptr, nullptr, out, 0, OUT_N);
}

// round 10
// speedup vs baseline: 4.1184x; 1.0742x over previous
#include <cuda_runtime.h>
#include <cuda_fp16.h>
#include <cuda_bf16.h>
#include <cstdint>

// ---------------------------------------------------------------------------
// TempoJelly R10: single-split fp16 HMMA GEMM + bounded candidate fixup.
//   s2 = ((x @ W1^T >= 1) @ W2^T >= 1), x binary.
//
//  - x, s1 in {0,1}: exact in fp16 (GEMM operand) and int8 (fixup dots)
//  - weights: hi = fp16(w) [GEMM], mid = bf16(w-hi) [fixup only]
//  - eps1_col = sum|w-hi| + MARGIN -> provable-side threshold, else candidate
//  - fixup1: t = acc + sum x*mid; fixup2 (rare): exact fp32 dot
//  GEMM: mma.m16n8k16.f32.f16, CTA 128xBN (BN=128 layer1 / 64 layer2 so
//  layer2 fills one full wave of 256 CTAs), 128 thr, 3-stage cp.async.
// ---------------------------------------------------------------------------

#define B_ROWS  4096
#define IN_K    3136
#define FEAT    6272
#define OUT_N   500
#define OUT_PAD 512
#define MAXC    (1 << 21)
#define MARGIN  3.0e-4f

// ---------------- static scratch --------------------------------------------
__device__ __align__(16) __half         g_xh  [(size_t)B_ROWS * IN_K];
__device__ __align__(16) int8_t         g_xi  [(size_t)B_ROWS * IN_K];
__device__ __align__(16) __half         g_w1h [(size_t)FEAT * IN_K];
__device__ __align__(16) __nv_bfloat16  g_w1m [(size_t)FEAT * IN_K];
__device__ __align__(16) __half         g_w2h [(size_t)OUT_PAD * FEAT];
__device__ __align__(16) __nv_bfloat16  g_w2m [(size_t)OUT_PAD * FEAT];
__device__ __align__(16) __half         g_s1h [(size_t)B_ROWS * FEAT];
__device__ __align__(16) int8_t         g_s1i [(size_t)B_ROWS * FEAT];
__device__ float g_e1a[FEAT],    g_e2a[FEAT];
__device__ float g_e1b[OUT_PAD], g_e2b[OUT_PAD];
__device__ uint32_t g_crc1[MAXC];
__device__ float    g_cv1 [MAXC];
__device__ uint32_t g_crc2[MAXC];
__device__ float    g_cv2 [MAXC];
__device__ uint32_t g_crc1e[MAXC];
__device__ uint32_t g_crc2e[MAXC];
__device__ uint32_t g_cnt[4];   // L1 cands, L1 final, L2 cands, L2 final

// ---------------- helpers ----------------------------------------------------
__device__ __forceinline__ uint32_t smem_u32(const void* p) {
    return (uint32_t)__cvta_generic_to_shared(p);
}
__device__ __forceinline__ uint32_t sw128(uint32_t off) {
    return off ^ ((off >> 3) & 0x70);
}

#define CP_ASYNC16(smaddr, gptr)                                               \
    asm volatile("cp.async.cg.shared.global [%0], [%1], 16;"                   \
                 :: "r"(smaddr), "l"(gptr))
#define CP_COMMIT() asm volatile("cp.async.commit_group;" ::: "memory")
#define CP_WAIT(n)  asm volatile("cp.async.wait_group %0;" :: "n"(n) : "memory")

#define LDSM_X4(r, addr)                                                       \
    asm volatile("ldmatrix.sync.aligned.m8n8.x4.shared.b16 {%0,%1,%2,%3}, [%4];" \
                 : "=r"((r)[0]), "=r"((r)[1]), "=r"((r)[2]), "=r"((r)[3])      \
                 : "r"(addr))

#define MMAF16(cc, aa, b0, b1)                                                 \
    asm volatile("mma.sync.aligned.m16n8k16.row.col.f32.f16.f16.f32 "          \
                 "{%0,%1,%2,%3},{%4,%5,%6,%7},{%8,%9},{%0,%1,%2,%3};"          \
                 : "+f"((cc)[0]), "+f"((cc)[1]), "+f"((cc)[2]), "+f"((cc)[3])  \
                 : "r"((aa)[0]), "r"((aa)[1]), "r"((aa)[2]), "r"((aa)[3]),     \
                   "r"(b0), "r"(b1))

// ---------------- prep kernels -----------------------------------------------
// x (fp32 0/1) -> fp16 (GEMM) + int8 (fixup); also resets candidate counters.
__global__ void cvt_x_kernel(const float* __restrict__ x,
                             __half* __restrict__ xh,
                             int8_t* __restrict__ xi) {
    if (blockIdx.x == 0 && threadIdx.x < 4) g_cnt[threadIdx.x] = 0;
    const size_t n4 = (size_t)B_ROWS * IN_K / 4;
    size_t i = (size_t)blockIdx.x * blockDim.x + threadIdx.x;
    const size_t stride = (size_t)gridDim.x * blockDim.x;
    for (; i < n4; i += stride) {
        const float4 v = reinterpret_cast<const float4*>(x)[i];
        const int b0 = (v.x != 0.0f), b1 = (v.y != 0.0f);
        const int b2 = (v.z != 0.0f), b3 = (v.w != 0.0f);
        const uint32_t h01 = (b0 ? 0x3C00u : 0u) | ((b1 ? 0x3C00u : 0u) << 16);
        const uint32_t h23 = (b2 ? 0x3C00u : 0u) | ((b3 ? 0x3C00u : 0u) << 16);
        reinterpret_cast<uint2*>(xh)[i] = make_uint2(h01, h23);
        reinterpret_cast<uchar4*>(xi)[i] =
            make_uchar4((unsigned char)b0, (unsigned char)b1,
                        (unsigned char)b2, (unsigned char)b3);
    }
}

// One warp per output column: hi=fp16(w), mid=bf16(w-hi), residual bounds.
__global__ void split_w_kernel(const float* __restrict__ W, int n_rows,
                               int rows_pad, int K,
                               __half* __restrict__ Wh,
                               __nv_bfloat16* __restrict__ Wm,
                               float* __restrict__ e1,
                               float* __restrict__ e2) {
    const int wid  = threadIdx.x >> 5;
    const int lane = threadIdx.x & 31;
    const int row  = blockIdx.x * (blockDim.x >> 5) + wid;
    if (row >= rows_pad) return;

    if (row >= n_rows) {   // pad row: zeros, never a candidate
        for (int i = lane * 4; i < K; i += 128) {
            *reinterpret_cast<uint2*>(Wh + (size_t)row * K + i) = make_uint2(0, 0);
            *reinterpret_cast<uint2*>(Wm + (size_t)row * K + i) = make_uint2(0, 0);
        }
        if (lane == 0) { e1[row] = -1.0f; e2[row] = -1.0f; }
        return;
    }

    float s1 = 0.0f, s2 = 0.0f;
    for (int i = lane * 4; i < K; i += 128) {
        const float4 v = *reinterpret_cast<const float4*>(W + (size_t)row * K + i);
        const float w[4] = {v.x, v.y, v.z, v.w};
        ushort hh[4], mm[4];
#pragma unroll
        for (int j = 0; j < 4; j++) {
            const __half h = __float2half_rn(w[j]);
            const float r = w[j] - __half2float(h);
            const __nv_bfloat16 m = __float2bfloat16_rn(r);
            const float r2 = r - __bfloat162float(m);
            s1 += fabsf(r);
            s2 += fabsf(r2);
            hh[j] = __half_as_ushort(h);
            mm[j] = __bfloat16_as_ushort(m);
        }
        *reinterpret_cast<uint2*>(Wh + (size_t)row * K + i) = make_uint2(
            (uint32_t)hh[0] | ((uint32_t)hh[1] << 16),
            (uint32_t)hh[2] | ((uint32_t)hh[3] << 16));
        *reinterpret_cast<uint2*>(Wm + (size_t)row * K + i) = make_uint2(
            (uint32_t)mm[0] | ((uint32_t)mm[1] << 16),
            (uint32_t)mm[2] | ((uint32_t)mm[3] << 16));
    }
#pragma unroll
    for (int o = 16; o; o >>= 1) {
        s1 += __shfl_xor_sync(~0u, s1, o);
        s2 += __shfl_xor_sync(~0u, s2, o);
    }
    if (lane == 0) {
        e1[row] = s1 + MARGIN;
        e2[row] = s2 + MARGIN;
    }
}

// ---------------- fp16 HMMA GEMM: CTA 128 x BN, 4 warps, 3 stages -------------
// BN=128: warp tile 64x64, stage 32KB (layer 1, grid 49x32)
// BN= 64: warp tile 64x32, stage 24KB (layer 2, grid 8x32 = 256 = one wave)
template <int BN>
__global__ __launch_bounds__(128, 2)
void spike_gemm_f16(const __half* __restrict__ A,
                    const __half* __restrict__ B,
                    const float* __restrict__ eps1,
                    __half* __restrict__ outH,       // dual-mode (layer 1)
                    int8_t* __restrict__ outI,
                    float* __restrict__ outF,        // fp32-mode (layer 2)
                    uint32_t* __restrict__ cand_rc,
                    float* __restrict__ cand_val,
                    uint32_t* __restrict__ cnt,
                    int K, int Nstride, int Nstore) {
    constexpr int NB = BN / 32;                  // 16-col groups per warp
    constexpr int STAGE = 16384 + BN * 128;      // A tile + B tile bytes
    constexpr int NSTG = 3;

    extern __shared__ char smem[];
    const uint32_t sbase = smem_u32(smem);
    const uint32_t data0 = (sbase + 1023u) & ~1023u;

    const int tid  = threadIdx.x;
    const int lane = tid & 31;
    const int wid  = tid >> 5;
    const int wm   = wid & 1;           // 2 warp-rows x 64
    const int wn   = wid >> 1;          // 2 warp-cols x BN/2
    const int bm   = blockIdx.y * 128;
    const int bn   = blockIdx.x * BN;
    const int K8   = K >> 3;
    const int nchunks = K >> 6;

    const int rA = lane & 15;
    const int kA = (lane >> 4) * 16;
    const int rB = ((lane >> 4) << 3) | (lane & 7);
    const int kB = ((lane >> 3) & 1) * 16;

    float acc[4][NB][8];
#pragma unroll
    for (int mt = 0; mt < 4; mt++)
#pragma unroll
        for (int nb = 0; nb < NB; nb++)
#pragma unroll
            for (int r = 0; r < 8; r++) acc[mt][nb][r] = 0.0f;

    auto load_chunk = [&](int ch) {
        uint32_t buf = data0 + (uint32_t)(ch % NSTG) * STAGE;
        const int k0u = ch << 3;
#pragma unroll
        for (int t = 0; t < 8; ++t) {
            const int u = tid + t * 128;
            const int row = u >> 3, ku = u & 7;
            const uint4* src = reinterpret_cast<const uint4*>(A)
                             + (size_t)(bm + row) * K8 + k0u + ku;
            CP_ASYNC16(buf + sw128(row * 128 + ku * 16), src);
        }
#pragma unroll
        for (int t = 0; t < BN / 16; ++t) {
            const int u = tid + t * 128;
            const int row = u >> 3, ku = u & 7;
            const uint4* src = reinterpret_cast<const uint4*>(B)
                             + (size_t)(bn + row) * K8 + k0u + ku;
            CP_ASYNC16(buf + 16384u + sw128(row * 128 + ku * 16), src);
        }
        CP_COMMIT();
    };

    load_chunk(0);
    load_chunk(1);

    for (int ch = 0; ch < nchunks; ++ch) {
        CP_WAIT(1);
        __syncthreads();

        if (ch + 2 < nchunks) load_chunk(ch + 2);
        else CP_COMMIT();                 // keep group count exact in tail

        const uint32_t buf = data0 + (uint32_t)(ch % NSTG) * STAGE;
#pragma unroll
        for (int ks = 0; ks < 4; ++ks) {
            uint32_t a[4][4];
#pragma unroll
            for (int mt = 0; mt < 4; mt++) {
                const uint32_t addr = buf
                    + sw128((wm * 64 + mt * 16 + rA) * 128 + ks * 32 + kA);
                LDSM_X4(a[mt], addr);
            }
#pragma unroll
            for (int nb = 0; nb < NB; nb++) {
                uint32_t b[4];
                const uint32_t addr = buf + 16384u
                    + sw128((wn * (BN / 2) + nb * 16 + rB) * 128 + ks * 32 + kB);
                LDSM_X4(b, addr);
#pragma unroll
                for (int mt = 0; mt < 4; mt++) {
                    MMAF16(acc[mt][nb] + 0, a[mt], b[0], b[1]);
                    MMAF16(acc[mt][nb] + 4, a[mt], b[2], b[3]);
                }
            }
        }
    }

    // ---- epilogue: threshold + candidate capture (with acc value) ----
    float ev[NB][2][2];
#pragma unroll
    for (int nb = 0; nb < NB; nb++)
#pragma unroll
        for (int h = 0; h < 2; h++) {
            const int col = bn + wn * (BN / 2) + nb * 16 + h * 8 + (lane & 3) * 2;
            ev[nb][h][0] = eps1[col];
            ev[nb][h][1] = eps1[col + 1];
        }

#pragma unroll
    for (int mt = 0; mt < 4; mt++) {
        const int row0 = bm + wm * 64 + mt * 16 + (lane >> 2);
#pragma unroll
        for (int nb = 0; nb < NB; nb++) {
#pragma unroll
            for (int h = 0; h < 2; h++) {
                const int col = bn + wn * (BN / 2) + nb * 16 + h * 8
                              + (lane & 3) * 2;
                const float* v = acc[mt][nb] + h * 4;
                int sp[4];
#pragma unroll
                for (int r = 0; r < 4; r++) {
                    sp[r] = (v[r] >= 1.0f);
                    const int colr = col + (r & 1);
                    if (fabsf(v[r] - 1.0f) <= ev[nb][h][r & 1] && colr < Nstore) {
                        const int rowr = row0 + (r >> 1) * 8;
                        const uint32_t idx = atomicAdd(cnt, 1u);
                        if (idx < MAXC) {
                            cand_rc[idx]  = ((uint32_t)rowr << 16) | (uint32_t)colr;
                            cand_val[idx] = v[r];
                        }
                    }
                }
                if (outF == nullptr) {    // dual fp16 + int8 (layer 1)
                    *reinterpret_cast<uint32_t*>(
                        outH + (size_t)row0 * Nstride + col) =
                        (sp[0] ? 0x3C00u : 0u) | ((sp[1] ? 0x3C00u : 0u) << 16);
                    *reinterpret_cast<uint32_t*>(
                        outH + (size_t)(row0 + 8) * Nstride + col) =
                        (sp[2] ? 0x3C00u : 0u) | ((sp[3] ? 0x3C00u : 0u) << 16);
                    *reinterpret_cast<uint16_t*>(
                        outI + (size_t)row0 * Nstride + col) =
                        (uint16_t)(sp[0] | (sp[1] << 8));
                    *reinterpret_cast<uint16_t*>(
                        outI + (size_t)(row0 + 8) * Nstride + col) =
                        (uint16_t)(sp[2] | (sp[3] << 8));
                } else if (col < Nstore) {  // fp32 (layer 2); 500 even -> pair-safe
                    *reinterpret_cast<float2*>(
                        outF + (size_t)row0 * Nstore + col) =
                        make_float2((float)sp[0], (float)sp[1]);
                    *reinterpret_cast<float2*>(
                        outF + (size_t)(row0 + 8) * Nstore + col) =
                        make_float2((float)sp[2], (float)sp[3]);
                }
            }
        }
    }
}

// ---------------- fixup 1: add mid-residual dot (int8 x * bf16 mid) ----------
__global__ void fixmid_kernel(const uint32_t* __restrict__ crc,
                              const float* __restrict__ cval,
                              const uint32_t* __restrict__ cntp,
                              const int8_t* __restrict__ X,
                              const __nv_bfloat16* __restrict__ Wm,
                              const float* __restrict__ e2,
                              int K,
                              __half* __restrict__ outH,
                              int8_t* __restrict__ outI,
                              float* __restrict__ outF,
                              int NstrideH, int NstrideF,
                              uint32_t* __restrict__ crc_e,
                              uint32_t* __restrict__ cnt_e) {
    const int gw   = (blockIdx.x * blockDim.x + threadIdx.x) >> 5;
    const int lane = threadIdx.x & 31;
    const int nw   = (gridDim.x * blockDim.x) >> 5;
    uint32_t n = *cntp; if (n > MAXC) n = MAXC;
    for (uint32_t i = gw; i < n; i += nw) {
        const uint32_t e = crc[i];
        const int row = (int)(e >> 16);
        const int col = (int)(e & 0xFFFFu);
        float dot = 0.0f;
        const int8_t* xr = X + (size_t)row * K;
        const __nv_bfloat16* mr = Wm + (size_t)col * K;
        for (int k = lane * 4; k < K; k += 128) {
            const char4 xv = *reinterpret_cast<const char4*>(xr + k);
            const uint2 mv = *reinterpret_cast<const uint2*>(mr + k);
            const float m0 = __bfloat162float(__ushort_as_bfloat16((ushort)(mv.x & 0xFFFF)));
            const float m1 = __bfloat162float(__ushort_as_bfloat16((ushort)(mv.x >> 16)));
            const float m2 = __bfloat162float(__ushort_as_bfloat16((ushort)(mv.y & 0xFFFF)));
            const float m3 = __bfloat162float(__ushort_as_bfloat16((ushort)(mv.y >> 16)));
            dot += xv.x * m0 + xv.y * m1 + xv.z * m2 + xv.w * m3;
        }
#pragma unroll
        for (int o = 16; o; o >>= 1) dot += __shfl_xor_sync(~0u, dot, o);
        if (lane == 0) {
            const float t = cval[i] + dot;
            if (fabsf(t - 1.0f) <= e2[col]) {
                const uint32_t idx = atomicAdd(cnt_e, 1u);
                if (idx < MAXC) crc_e[idx] = e;
            } else {
                const int spike = (t >= 1.0f);
                if (outF == nullptr) {
                    outH[(size_t)row * NstrideH + col] =
                        __ushort_as_half(spike ? (ushort)0x3C00 : (ushort)0);
                    outI[(size_t)row * NstrideH + col] = (int8_t)spike;
                } else {
                    outF[(size_t)row * NstrideF + col] = (float)spike;
                }
            }
        }
    }
}

// ---------------- fixup 2: exact fp32 dot -------------------------------------
__global__ void fixe_kernel(const uint32_t* __restrict__ crc,
                            const uint32_t* __restrict__ cntp,
                            const int8_t* __restrict__ X,
                            const float* __restrict__ W, int K,
                            __half* __restrict__ outH,
                            int8_t* __restrict__ outI,
                            float* __restrict__ outF,
                            int NstrideH, int NstrideF) {
    const int gw   = (blockIdx.x * blockDim.x + threadIdx.x) >> 5;
    const int lane = threadIdx.x & 31;
    const int nw   = (gridDim.x * blockDim.x) >> 5;
    uint32_t n = *cntp; if (n > MAXC) n = MAXC;
    for (uint32_t i = gw; i < n; i += nw) {
        const uint32_t e = crc[i];
        const int row = (int)(e >> 16);
        const int col = (int)(e & 0xFFFFu);
        float s = 0.0f;
        for (int k = lane; k < K; k += 32)
            s += (float)X[(size_t)row * K + k] * W[(size_t)col * K + k];
#pragma unroll
        for (int o = 16; o; o >>= 1) s += __shfl_xor_sync(~0u, s, o);
        if (lane == 0) {
            const int spike = (s >= 1.0f);
            if (outF == nullptr) {
                outH[(size_t)row * NstrideH + col] =
                    __ushort_as_half(spike ? (ushort)0x3C00 : (ushort)0);
                outI[(size_t)row * NstrideH + col] = (int8_t)spike;
            } else {
                outF[(size_t)row * NstrideF + col] = (float)spike;
            }
        }
    }
}

// ---------------- host launch --------------------------------------------------
extern "C" void kernel_launch(void* const* d_in, const int* in_sizes, int n_in,
                              void* d_out, int out_size) {
    const float* x  = (const float*)d_in[0];
    const float* W1 = (const float*)d_in[1];
    const float* W2 = (const float*)d_in[2];
    float* out = (float*)d_out;

    __half *xh, *w1h, *w2h, *s1h;
    __nv_bfloat16 *w1m, *w2m;
    int8_t *xi, *s1i;
    float *e1a, *e2a, *e1b, *e2b, *cv1, *cv2;
    uint32_t *crc1, *crc2, *crc1e, *crc2e, *cnt;
    cudaGetSymbolAddress((void**)&xh,  g_xh);
    cudaGetSymbolAddress((void**)&xi,  g_xi);
    cudaGetSymbolAddress((void**)&w1h, g_w1h);
    cudaGetSymbolAddress((void**)&w1m, g_w1m);
    cudaGetSymbolAddress((void**)&w2h, g_w2h);
    cudaGetSymbolAddress((void**)&w2m, g_w2m);
    cudaGetSymbolAddress((void**)&s1h, g_s1h);
    cudaGetSymbolAddress((void**)&s1i, g_s1i);
    cudaGetSymbolAddress((void**)&e1a, g_e1a);
    cudaGetSymbolAddress((void**)&e2a, g_e2a);
    cudaGetSymbolAddress((void**)&e1b, g_e1b);
    cudaGetSymbolAddress((void**)&e2b, g_e2b);
    cudaGetSymbolAddress((void**)&crc1,  g_crc1);
    cudaGetSymbolAddress((void**)&cv1,   g_cv1);
    cudaGetSymbolAddress((void**)&crc2,  g_crc2);
    cudaGetSymbolAddress((void**)&cv2,   g_cv2);
    cudaGetSymbolAddress((void**)&crc1e, g_crc1e);
    cudaGetSymbolAddress((void**)&crc2e, g_crc2e);
    cudaGetSymbolAddress((void**)&cnt,   g_cnt);

    const int smem1 = 1024 + 3 * (16384 + 128 * 128);   // BN=128: 99328
    const int smem2 = 1024 + 3 * (16384 + 64 * 128);    // BN= 64: 74752
    cudaFuncSetAttribute(spike_gemm_f16<128>,
                         cudaFuncAttributeMaxDynamicSharedMemorySize, smem1);
    cudaFuncSetAttribute(spike_gemm_f16<64>,
                         cudaFuncAttributeMaxDynamicSharedMemorySize, smem2);

    cvt_x_kernel<<<2048, 256>>>(x, xh, xi);   // also resets g_cnt
    split_w_kernel<<<FEAT / 8, 256>>>(W1, FEAT, FEAT, IN_K, w1h, w1m, e1a, e2a);
    split_w_kernel<<<OUT_PAD / 8, 256>>>(W2, OUT_N, OUT_PAD, FEAT,
                                         w2h, w2m, e1b, e2b);

    // Layer 1: s1 = (x @ W1^T >= 1)  -> dual fp16 + int8   (BN=128)
    {
        dim3 grid(FEAT / 128, B_ROWS / 128);   // (49, 32)
        spike_gemm_f16<128><<<grid, 128, smem1>>>(
            xh, w1h, e1a, s1h, s1i, nullptr,
            crc1, cv1, cnt + 0, IN_K, FEAT, FEAT);
    }
    fixmid_kernel<<<1024, 256>>>(crc1, cv1, cnt + 0, xi, w1m, e2a, IN_K,
                                 s1h, s1i, nullptr, FEAT, 0, crc1e, cnt + 1);
    fixe_kernel<<<512, 256>>>(crc1e, cnt + 1, xi, W1, IN_K,
                              s1h, s1i, nullptr, FEAT, 0);

    // Layer 2: out = (s1 @ W2^T >= 1)  -> fp32   (BN=64, 256 CTAs = 1 wave)
    {
        dim3 grid(OUT_PAD / 64, B_ROWS / 128);  // (8, 32)
        spike_gemm_f16<64><<<grid, 128, smem2>>>(
            s1h, w2h, e1b, nullptr, nullptr, out,
            crc2, cv2, cnt + 2, FEAT, OUT_N, OUT_N);
    }
    fixmid_kernel<<<1024, 256>>>(crc2, cv2, cnt + 2, s1i, w2m, e2b, FEAT,
                                 nullptr, nullptr, out, 0, OUT_N, crc2e, cnt + 3);
    fixe_kernel<<<512, 256>>>(crc2e, cnt + 3, s1i, W2, FEAT,
                              nullptr, nullptr, out, 0, OUT_N);
}

// round 12
// speedup vs baseline: 4.2198x; 1.0246x over previous
#include <cuda_runtime.h>
#include <cuda_fp16.h>
#include <cuda_bf16.h>
#include <cstdint>

// ---------------------------------------------------------------------------
// TempoJelly R11: single-split fp16 HMMA GEMM + int8-digit candidate fixup.
//   s2 = ((x @ W1^T >= 1) @ W2^T >= 1), x binary.
//
//  - x, s1 in {0,1}: exact in fp16 (GEMM operand) and int8 (fixup dots)
//  - weights: hi = fp16(w) [GEMM]; residual r = w - hi quantized to int8
//    digit m = round(r * S_col), S_col = 127/max|r|  [fixup only]
//  - eps1_col = sum|r| + MARGIN -> provable-side threshold, else candidate
//  - fixup1: t = acc + (sum x*m via dp4a, exact s32) * invS_col
//    eps2_col = sum|r - m*invS| + MARGIN  (computed with the same arithmetic)
//  - fixup2 (rare): exact fp32 dot vs original W
//  GEMM: mma.m16n8k16.f32.f16, CTA 128xBN (BN=128 L1 / 64 L2), 128 thr,
//  4 warps of 64x(BN/2), 3-stage cp.async, 2 CTAs/SM.
// ---------------------------------------------------------------------------

#define B_ROWS  4096
#define IN_K    3136
#define FEAT    6272
#define OUT_N   500
#define OUT_PAD 512
#define MAXC    (1 << 21)
#define MARGIN  3.0e-4f

// ---------------- static scratch --------------------------------------------
__device__ __align__(16) __half  g_xh  [(size_t)B_ROWS * IN_K];
__device__ __align__(16) int8_t  g_xi  [(size_t)B_ROWS * IN_K];
__device__ __align__(16) __half  g_w1h [(size_t)FEAT * IN_K];
__device__ __align__(16) int8_t  g_w1m [(size_t)FEAT * IN_K];
__device__ __align__(16) __half  g_w2h [(size_t)OUT_PAD * FEAT];
__device__ __align__(16) int8_t  g_w2m [(size_t)OUT_PAD * FEAT];
__device__ __align__(16) __half  g_s1h [(size_t)B_ROWS * FEAT];
__device__ __align__(16) int8_t  g_s1i [(size_t)B_ROWS * FEAT];
__device__ float g_e1a[FEAT],    g_e2a[FEAT],    g_is1[FEAT];
__device__ float g_e1b[OUT_PAD], g_e2b[OUT_PAD], g_is2[OUT_PAD];
__device__ uint32_t g_crc1[MAXC];
__device__ float    g_cv1 [MAXC];
__device__ uint32_t g_crc2[MAXC];
__device__ float    g_cv2 [MAXC];
__device__ uint32_t g_crc1e[MAXC];
__device__ uint32_t g_crc2e[MAXC];
__device__ uint32_t g_cnt[4];   // L1 cands, L1 final, L2 cands, L2 final

// ---------------- helpers ----------------------------------------------------
__device__ __forceinline__ uint32_t smem_u32(const void* p) {
    return (uint32_t)__cvta_generic_to_shared(p);
}
__device__ __forceinline__ uint32_t sw128(uint32_t off) {
    return off ^ ((off >> 3) & 0x70);
}
__device__ __forceinline__ int dp4a_s(uint32_t a, uint32_t b, int c) {
    return __dp4a((int)a, (int)b, c);
}

#define CP_ASYNC16(smaddr, gptr)                                               \
    asm volatile("cp.async.cg.shared.global [%0], [%1], 16;"                   \
                 :: "r"(smaddr), "l"(gptr))
#define CP_COMMIT() asm volatile("cp.async.commit_group;" ::: "memory")
#define CP_WAIT(n)  asm volatile("cp.async.wait_group %0;" :: "n"(n) : "memory")

#define LDSM_X4(r, addr)                                                       \
    asm volatile("ldmatrix.sync.aligned.m8n8.x4.shared.b16 {%0,%1,%2,%3}, [%4];" \
                 : "=r"((r)[0]), "=r"((r)[1]), "=r"((r)[2]), "=r"((r)[3])      \
                 : "r"(addr))

#define MMAF16(cc, aa, b0, b1)                                                 \
    asm volatile("mma.sync.aligned.m16n8k16.row.col.f32.f16.f16.f32 "          \
                 "{%0,%1,%2,%3},{%4,%5,%6,%7},{%8,%9},{%0,%1,%2,%3};"          \
                 : "+f"((cc)[0]), "+f"((cc)[1]), "+f"((cc)[2]), "+f"((cc)[3])  \
                 : "r"((aa)[0]), "r"((aa)[1]), "r"((aa)[2]), "r"((aa)[3]),     \
                   "r"(b0), "r"(b1))

// ---------------- prep kernels -----------------------------------------------
// x (fp32 0/1) -> fp16 (GEMM) + int8 (fixup); also resets candidate counters.
__global__ void cvt_x_kernel(const float* __restrict__ x,
                             __half* __restrict__ xh,
                             int8_t* __restrict__ xi) {
    if (blockIdx.x == 0 && threadIdx.x < 4) g_cnt[threadIdx.x] = 0;
    const size_t n4 = (size_t)B_ROWS * IN_K / 4;
    size_t i = (size_t)blockIdx.x * blockDim.x + threadIdx.x;
    const size_t stride = (size_t)gridDim.x * blockDim.x;
    for (; i < n4; i += stride) {
        const float4 v = reinterpret_cast<const float4*>(x)[i];
        const int b0 = (v.x != 0.0f), b1 = (v.y != 0.0f);
        const int b2 = (v.z != 0.0f), b3 = (v.w != 0.0f);
        const uint32_t h01 = (b0 ? 0x3C00u : 0u) | ((b1 ? 0x3C00u : 0u) << 16);
        const uint32_t h23 = (b2 ? 0x3C00u : 0u) | ((b3 ? 0x3C00u : 0u) << 16);
        reinterpret_cast<uint2*>(xh)[i] = make_uint2(h01, h23);
        reinterpret_cast<uchar4*>(xi)[i] =
            make_uchar4((unsigned char)b0, (unsigned char)b1,
                        (unsigned char)b2, (unsigned char)b3);
    }
}

// One warp per output column: hi=fp16(w); residual r -> int8 digit m with
// per-column scale; bounds e1 = sum|r|, e2 = sum|r - m*invS| (exact arith).
__global__ void split_w_kernel(const float* __restrict__ W, int n_rows,
                               int rows_pad, int K,
                               __half* __restrict__ Wh,
                               int8_t* __restrict__ Wm,
                               float* __restrict__ e1,
                               float* __restrict__ e2,
                               float* __restrict__ invSo) {
    const int wid  = threadIdx.x >> 5;
    const int lane = threadIdx.x & 31;
    const int row  = blockIdx.x * (blockDim.x >> 5) + wid;
    if (row >= rows_pad) return;

    if (row >= n_rows) {   // pad row: zeros, never a candidate
        for (int i = lane * 4; i < K; i += 128) {
            *reinterpret_cast<uint2*>(Wh + (size_t)row * K + i) = make_uint2(0, 0);
            *reinterpret_cast<char4*>(Wm + (size_t)row * K + i) = make_char4(0,0,0,0);
        }
        if (lane == 0) { e1[row] = -1.0f; e2[row] = -1.0f; invSo[row] = 0.0f; }
        return;
    }

    // pass 1: hi split, e1 sum, max|r|
    float s1 = 0.0f, mr = 0.0f;
    for (int i = lane * 4; i < K; i += 128) {
        const float4 v = *reinterpret_cast<const float4*>(W + (size_t)row * K + i);
        const float w[4] = {v.x, v.y, v.z, v.w};
        ushort hh[4];
#pragma unroll
        for (int j = 0; j < 4; j++) {
            const __half h = __float2half_rn(w[j]);
            const float r = w[j] - __half2float(h);
            s1 += fabsf(r);
            mr = fmaxf(mr, fabsf(r));
            hh[j] = __half_as_ushort(h);
        }
        *reinterpret_cast<uint2*>(Wh + (size_t)row * K + i) = make_uint2(
            (uint32_t)hh[0] | ((uint32_t)hh[1] << 16),
            (uint32_t)hh[2] | ((uint32_t)hh[3] << 16));
    }
#pragma unroll
    for (int o = 16; o; o >>= 1) {
        s1 += __shfl_xor_sync(~0u, s1, o);
        mr = fmaxf(mr, __shfl_xor_sync(~0u, mr, o));
    }
    const float S    = (mr > 0.0f) ? (127.0f / mr) : 1.0f;
    const float invS = (mr > 0.0f) ? (mr / 127.0f) : 0.0f;

    // pass 2: quantize digit, exact post-fixup bound
    float s2 = 0.0f;
    for (int i = lane * 4; i < K; i += 128) {
        const float4 v = *reinterpret_cast<const float4*>(W + (size_t)row * K + i);
        const float w[4] = {v.x, v.y, v.z, v.w};
        char mm[4];
#pragma unroll
        for (int j = 0; j < 4; j++) {
            const __half h = __float2half_rn(w[j]);
            const float r = w[j] - __half2float(h);
            int q = __float2int_rn(r * S);
            q = max(-127, min(127, q));
            s2 += fabsf(fmaf(-(float)q, invS, r));   // |r - m*invS|
            mm[j] = (char)q;
        }
        *reinterpret_cast<char4*>(Wm + (size_t)row * K + i) =
            make_char4(mm[0], mm[1], mm[2], mm[3]);
    }
#pragma unroll
    for (int o = 16; o; o >>= 1) s2 += __shfl_xor_sync(~0u, s2, o);
    if (lane == 0) {
        e1[row] = s1 + MARGIN;
        e2[row] = s2 + MARGIN;
        invSo[row] = invS;
    }
}

// ---------------- fp16 HMMA GEMM: CTA 128 x BN, 4 warps, 3 stages -------------
template <int BN>
__global__ __launch_bounds__(128, 2)
void spike_gemm_f16(const __half* __restrict__ A,
                    const __half* __restrict__ B,
                    const float* __restrict__ eps1,
                    __half* __restrict__ outH,       // dual-mode (layer 1)
                    int8_t* __restrict__ outI,
                    float* __restrict__ outF,        // fp32-mode (layer 2)
                    uint32_t* __restrict__ cand_rc,
                    float* __restrict__ cand_val,
                    uint32_t* __restrict__ cnt,
                    int K, int Nstride, int Nstore) {
    constexpr int NB = BN / 32;
    constexpr int STAGE = 16384 + BN * 128;
    constexpr int NSTG = 3;

    extern __shared__ char smem[];
    const uint32_t sbase = smem_u32(smem);
    const uint32_t data0 = (sbase + 1023u) & ~1023u;

    const int tid  = threadIdx.x;
    const int lane = tid & 31;
    const int wid  = tid >> 5;
    const int wm   = wid & 1;
    const int wn   = wid >> 1;
    const int bm   = blockIdx.y * 128;
    const int bn   = blockIdx.x * BN;
    const int K8   = K >> 3;
    const int nchunks = K >> 6;

    const int rA = lane & 15;
    const int kA = (lane >> 4) * 16;
    const int rB = ((lane >> 4) << 3) | (lane & 7);
    const int kB = ((lane >> 3) & 1) * 16;

    float acc[4][NB][8];
#pragma unroll
    for (int mt = 0; mt < 4; mt++)
#pragma unroll
        for (int nb = 0; nb < NB; nb++)
#pragma unroll
            for (int r = 0; r < 8; r++) acc[mt][nb][r] = 0.0f;

    auto load_chunk = [&](int ch) {
        uint32_t buf = data0 + (uint32_t)(ch % NSTG) * STAGE;
        const int k0u = ch << 3;
#pragma unroll
        for (int t = 0; t < 8; ++t) {
            const int u = tid + t * 128;
            const int row = u >> 3, ku = u & 7;
            const uint4* src = reinterpret_cast<const uint4*>(A)
                             + (size_t)(bm + row) * K8 + k0u + ku;
            CP_ASYNC16(buf + sw128(row * 128 + ku * 16), src);
        }
#pragma unroll
        for (int t = 0; t < BN / 16; ++t) {
            const int u = tid + t * 128;
            const int row = u >> 3, ku = u & 7;
            const uint4* src = reinterpret_cast<const uint4*>(B)
                             + (size_t)(bn + row) * K8 + k0u + ku;
            CP_ASYNC16(buf + 16384u + sw128(row * 128 + ku * 16), src);
        }
        CP_COMMIT();
    };

    load_chunk(0);
    load_chunk(1);

    for (int ch = 0; ch < nchunks; ++ch) {
        CP_WAIT(1);
        __syncthreads();

        if (ch + 2 < nchunks) load_chunk(ch + 2);
        else CP_COMMIT();

        const uint32_t buf = data0 + (uint32_t)(ch % NSTG) * STAGE;
#pragma unroll
        for (int ks = 0; ks < 4; ++ks) {
            uint32_t a[4][4];
#pragma unroll
            for (int mt = 0; mt < 4; mt++) {
                const uint32_t addr = buf
                    + sw128((wm * 64 + mt * 16 + rA) * 128 + ks * 32 + kA);
                LDSM_X4(a[mt], addr);
            }
#pragma unroll
            for (int nb = 0; nb < NB; nb++) {
                uint32_t b[4];
                const uint32_t addr = buf + 16384u
                    + sw128((wn * (BN / 2) + nb * 16 + rB) * 128 + ks * 32 + kB);
                LDSM_X4(b, addr);
#pragma unroll
                for (int mt = 0; mt < 4; mt++) {
                    MMAF16(acc[mt][nb] + 0, a[mt], b[0], b[1]);
                    MMAF16(acc[mt][nb] + 4, a[mt], b[2], b[3]);
                }
            }
        }
    }

    // ---- epilogue: threshold + candidate capture ----
    float ev[NB][2][2];
#pragma unroll
    for (int nb = 0; nb < NB; nb++)
#pragma unroll
        for (int h = 0; h < 2; h++) {
            const int col = bn + wn * (BN / 2) + nb * 16 + h * 8 + (lane & 3) * 2;
            ev[nb][h][0] = eps1[col];
            ev[nb][h][1] = eps1[col + 1];
        }

#pragma unroll
    for (int mt = 0; mt < 4; mt++) {
        const int row0 = bm + wm * 64 + mt * 16 + (lane >> 2);
#pragma unroll
        for (int nb = 0; nb < NB; nb++) {
#pragma unroll
            for (int h = 0; h < 2; h++) {
                const int col = bn + wn * (BN / 2) + nb * 16 + h * 8
                              + (lane & 3) * 2;
                const float* v = acc[mt][nb] + h * 4;
                int sp[4];
#pragma unroll
                for (int r = 0; r < 4; r++) {
                    sp[r] = (v[r] >= 1.0f);
                    const int colr = col + (r & 1);
                    if (fabsf(v[r] - 1.0f) <= ev[nb][h][r & 1] && colr < Nstore) {
                        const int rowr = row0 + (r >> 1) * 8;
                        const uint32_t idx = atomicAdd(cnt, 1u);
                        if (idx < MAXC) {
                            cand_rc[idx]  = ((uint32_t)rowr << 16) | (uint32_t)colr;
                            cand_val[idx] = v[r];
                        }
                    }
                }
                if (outF == nullptr) {
                    *reinterpret_cast<uint32_t*>(
                        outH + (size_t)row0 * Nstride + col) =
                        (sp[0] ? 0x3C00u : 0u) | ((sp[1] ? 0x3C00u : 0u) << 16);
                    *reinterpret_cast<uint32_t*>(
                        outH + (size_t)(row0 + 8) * Nstride + col) =
                        (sp[2] ? 0x3C00u : 0u) | ((sp[3] ? 0x3C00u : 0u) << 16);
                    *reinterpret_cast<uint16_t*>(
                        outI + (size_t)row0 * Nstride + col) =
                        (uint16_t)(sp[0] | (sp[1] << 8));
                    *reinterpret_cast<uint16_t*>(
                        outI + (size_t)(row0 + 8) * Nstride + col) =
                        (uint16_t)(sp[2] | (sp[3] << 8));
                } else if (col < Nstore) {
                    *reinterpret_cast<float2*>(
                        outF + (size_t)row0 * Nstore + col) =
                        make_float2((float)sp[0], (float)sp[1]);
                    *reinterpret_cast<float2*>(
                        outF + (size_t)(row0 + 8) * Nstore + col) =
                        make_float2((float)sp[2], (float)sp[3]);
                }
            }
        }
    }
}

// ---------------- fixup 1: int8-digit dot via dp4a ---------------------------
__global__ void fixmid_kernel(const uint32_t* __restrict__ crc,
                              const float* __restrict__ cval,
                              const uint32_t* __restrict__ cntp,
                              const int8_t* __restrict__ X,
                              const int8_t* __restrict__ Wm,
                              const float* __restrict__ e2,
                              const float* __restrict__ invS,
                              int K,
                              __half* __restrict__ outH,
                              int8_t* __restrict__ outI,
                              float* __restrict__ outF,
                              int NstrideH, int NstrideF,
                              uint32_t* __restrict__ crc_e,
                              uint32_t* __restrict__ cnt_e) {
    const int gw   = (blockIdx.x * blockDim.x + threadIdx.x) >> 5;
    const int lane = threadIdx.x & 31;
    const int nw   = (gridDim.x * blockDim.x) >> 5;
    uint32_t n = *cntp; if (n > MAXC) n = MAXC;
    const int K16 = K >> 4;
    for (uint32_t i = gw; i < n; i += nw) {
        const uint32_t e = crc[i];
        const int row = (int)(e >> 16);
        const int col = (int)(e & 0xFFFFu);
        int sc = 0;
        const uint4* xr = reinterpret_cast<const uint4*>(X)  + (size_t)row * K16;
        const uint4* mr = reinterpret_cast<const uint4*>(Wm) + (size_t)col * K16;
        for (int u = lane; u < K16; u += 32) {
            const uint4 xv = xr[u];
            const uint4 mv = mr[u];
            sc = dp4a_s(xv.x, mv.x, sc);
            sc = dp4a_s(xv.y, mv.y, sc);
            sc = dp4a_s(xv.z, mv.z, sc);
            sc = dp4a_s(xv.w, mv.w, sc);
        }
#pragma unroll
        for (int o = 16; o; o >>= 1) sc += __shfl_xor_sync(~0u, sc, o);
        if (lane == 0) {
            const float t = cval[i] + (float)sc * invS[col];
            if (fabsf(t - 1.0f) <= e2[col]) {
                const uint32_t idx = atomicAdd(cnt_e, 1u);
                if (idx < MAXC) crc_e[idx] = e;
            } else {
                const int spike = (t >= 1.0f);
                if (outF == nullptr) {
                    outH[(size_t)row * NstrideH + col] =
                        __ushort_as_half(spike ? (ushort)0x3C00 : (ushort)0);
                    outI[(size_t)row * NstrideH + col] = (int8_t)spike;
                } else {
                    outF[(size_t)row * NstrideF + col] = (float)spike;
                }
            }
        }
    }
}

// ---------------- fixup 2: exact fp32 dot -------------------------------------
__global__ void fixe_kernel(const uint32_t* __restrict__ crc,
                            const uint32_t* __restrict__ cntp,
                            const int8_t* __restrict__ X,
                            const float* __restrict__ W, int K,
                            __half* __restrict__ outH,
                            int8_t* __restrict__ outI,
                            float* __restrict__ outF,
                            int NstrideH, int NstrideF) {
    const int gw   = (blockIdx.x * blockDim.x + threadIdx.x) >> 5;
    const int lane = threadIdx.x & 31;
    const int nw   = (gridDim.x * blockDim.x) >> 5;
    uint32_t n = *cntp; if (n > MAXC) n = MAXC;
    for (uint32_t i = gw; i < n; i += nw) {
        const uint32_t e = crc[i];
        const int row = (int)(e >> 16);
        const int col = (int)(e & 0xFFFFu);
        float s = 0.0f;
        for (int k = lane; k < K; k += 32)
            s += (float)X[(size_t)row * K + k] * W[(size_t)col * K + k];
#pragma unroll
        for (int o = 16; o; o >>= 1) s += __shfl_xor_sync(~0u, s, o);
        if (lane == 0) {
            const int spike = (s >= 1.0f);
            if (outF == nullptr) {
                outH[(size_t)row * NstrideH + col] =
                    __ushort_as_half(spike ? (ushort)0x3C00 : (ushort)0);
                outI[(size_t)row * NstrideH + col] = (int8_t)spike;
            } else {
                outF[(size_t)row * NstrideF + col] = (float)spike;
            }
        }
    }
}

// ---------------- host launch --------------------------------------------------
extern "C" void kernel_launch(void* const* d_in, const int* in_sizes, int n_in,
                              void* d_out, int out_size) {
    const float* x  = (const float*)d_in[0];
    const float* W1 = (const float*)d_in[1];
    const float* W2 = (const float*)d_in[2];
    float* out = (float*)d_out;

    __half *xh, *w1h, *w2h, *s1h;
    int8_t *xi, *w1m, *w2m, *s1i;
    float *e1a, *e2a, *is1, *e1b, *e2b, *is2, *cv1, *cv2;
    uint32_t *crc1, *crc2, *crc1e, *crc2e, *cnt;
    cudaGetSymbolAddress((void**)&xh,  g_xh);
    cudaGetSymbolAddress((void**)&xi,  g_xi);
    cudaGetSymbolAddress((void**)&w1h, g_w1h);
    cudaGetSymbolAddress((void**)&w1m, g_w1m);
    cudaGetSymbolAddress((void**)&w2h, g_w2h);
    cudaGetSymbolAddress((void**)&w2m, g_w2m);
    cudaGetSymbolAddress((void**)&s1h, g_s1h);
    cudaGetSymbolAddress((void**)&s1i, g_s1i);
    cudaGetSymbolAddress((void**)&e1a, g_e1a);
    cudaGetSymbolAddress((void**)&e2a, g_e2a);
    cudaGetSymbolAddress((void**)&is1, g_is1);
    cudaGetSymbolAddress((void**)&e1b, g_e1b);
    cudaGetSymbolAddress((void**)&e2b, g_e2b);
    cudaGetSymbolAddress((void**)&is2, g_is2);
    cudaGetSymbolAddress((void**)&crc1,  g_crc1);
    cudaGetSymbolAddress((void**)&cv1,   g_cv1);
    cudaGetSymbolAddress((void**)&crc2,  g_crc2);
    cudaGetSymbolAddress((void**)&cv2,   g_cv2);
    cudaGetSymbolAddress((void**)&crc1e, g_crc1e);
    cudaGetSymbolAddress((void**)&crc2e, g_crc2e);
    cudaGetSymbolAddress((void**)&cnt,   g_cnt);

    const int smem1 = 1024 + 3 * (16384 + 128 * 128);   // BN=128: 99328
    const int smem2 = 1024 + 3 * (16384 + 64 * 128);    // BN= 64: 74752
    cudaFuncSetAttribute(spike_gemm_f16<128>,
                         cudaFuncAttributeMaxDynamicSharedMemorySize, smem1);
    cudaFuncSetAttribute(spike_gemm_f16<64>,
                         cudaFuncAttributeMaxDynamicSharedMemorySize, smem2);

    cvt_x_kernel<<<2048, 256>>>(x, xh, xi);   // also resets g_cnt
    split_w_kernel<<<FEAT / 8, 256>>>(W1, FEAT, FEAT, IN_K,
                                      w1h, w1m, e1a, e2a, is1);
    split_w_kernel<<<OUT_PAD / 8, 256>>>(W2, OUT_N, OUT_PAD, FEAT,
                                         w2h, w2m, e1b, e2b, is2);

    // Layer 1: s1 = (x @ W1^T >= 1)  -> dual fp16 + int8   (BN=128)
    {
        dim3 grid(FEAT / 128, B_ROWS / 128);   // (49, 32)
        spike_gemm_f16<128><<<grid, 128, smem1>>>(
            xh, w1h, e1a, s1h, s1i, nullptr,
            crc1, cv1, cnt + 0, IN_K, FEAT, FEAT);
    }
    fixmid_kernel<<<1024, 256>>>(crc1, cv1, cnt + 0, xi, w1m, e2a, is1, IN_K,
                                 s1h, s1i, nullptr, FEAT, 0, crc1e, cnt + 1);
    fixe_kernel<<<512, 256>>>(crc1e, cnt + 1, xi, W1, IN_K,
                              s1h, s1i, nullptr, FEAT, 0);

    // Layer 2: out = (s1 @ W2^T >= 1)  -> fp32   (BN=64, 256 CTAs = 1 wave)
    {
        dim3 grid(OUT_PAD / 64, B_ROWS / 128);  // (8, 32)
        spike_gemm_f16<64><<<grid, 128, smem2>>>(
            s1h, w2h, e1b, nullptr, nullptr, out,
            crc2, cv2, cnt + 2, FEAT, OUT_N, OUT_N);
    }
    fixmid_kernel<<<1024, 256>>>(crc2, cv2, cnt + 2, s1i, w2m, e2b, is2, FEAT,
                                 nullptr, nullptr, out, 0, OUT_N, crc2e, cnt + 3);
    fixe_kernel<<<512, 256>>>(crc2e, cnt + 3, s1i, W2, FEAT,
                              nullptr, nullptr, out, 0, OUT_N);
}